// round 1
// baseline (speedup 1.0000x reference)
#include <cuda_runtime.h>
#include <math.h>

// Problem constants
#define BB   4
#define SEQ  1024
#define DM   1024
#define NH   16
#define HD   64
#define FFD  4096
#define TOK  (BB*SEQ)   // 4096

// ---------------- scratch (device globals: no allocs allowed) ----------------
__device__ float g_q  [TOK*DM];
__device__ float g_k  [TOK*DM];
__device__ float g_v  [TOK*DM];
__device__ float g_ao [TOK*DM];
__device__ float g_z  [TOK*DM];
__device__ float g_o1 [TOK*DM];
__device__ float g_o2 [TOK*DM];
__device__ float g_ff [TOK*FFD];

// ---------------- GEMM: C[M,N] = A[M,K] @ W[K,N] + bias (opt ReLU) -----------
// 128x128x16 tile, 256 threads, 8x8 microtile with split-64 column mapping.
template<bool RELU>
__global__ __launch_bounds__(256)
void gemm_kernel(const float* __restrict__ A, const float* __restrict__ W,
                 const float* __restrict__ bias, float* __restrict__ C,
                 int M, int N, int K)
{
    __shared__ float As[16][132];
    __shared__ float Bs[16][132];
    const int tid  = threadIdx.x;
    const int tx   = tid & 15;
    const int ty   = tid >> 4;
    const int row0 = blockIdx.y * 128;
    const int col0 = blockIdx.x * 128;

    float acc[8][8];
#pragma unroll
    for (int i = 0; i < 8; i++)
#pragma unroll
        for (int j = 0; j < 8; j++) acc[i][j] = 0.f;

    const int ar = tid >> 2;         // 0..63
    const int ak = (tid & 3) * 4;    // 0,4,8,12
    const int br = tid >> 5;         // 0..7
    const int bc = (tid & 31) * 4;   // 0..124

    for (int k0 = 0; k0 < K; k0 += 16) {
#pragma unroll
        for (int i = 0; i < 2; i++) {
            const float4 a = *(const float4*)&A[(size_t)(row0 + ar + i*64)*K + k0 + ak];
            As[ak+0][ar + i*64] = a.x;
            As[ak+1][ar + i*64] = a.y;
            As[ak+2][ar + i*64] = a.z;
            As[ak+3][ar + i*64] = a.w;
        }
#pragma unroll
        for (int i = 0; i < 2; i++) {
            *(float4*)&Bs[br + i*8][bc] =
                *(const float4*)&W[(size_t)(k0 + br + i*8)*N + col0 + bc];
        }
        __syncthreads();
#pragma unroll
        for (int kk = 0; kk < 16; kk++) {
            float a[8], b[8];
            *(float4*)&a[0] = *(float4*)&As[kk][ty*4];
            *(float4*)&a[4] = *(float4*)&As[kk][64 + ty*4];
            *(float4*)&b[0] = *(float4*)&Bs[kk][tx*4];
            *(float4*)&b[4] = *(float4*)&Bs[kk][64 + tx*4];
#pragma unroll
            for (int i = 0; i < 8; i++)
#pragma unroll
                for (int j = 0; j < 8; j++)
                    acc[i][j] = fmaf(a[i], b[j], acc[i][j]);
        }
        __syncthreads();
    }
    // epilogue: rows {ty*4+i, 64+ty*4+i}, cols {tx*4+j, 64+tx*4+j}
#pragma unroll
    for (int i = 0; i < 8; i++) {
        const int r = row0 + ((i < 4) ? (ty*4 + i) : (64 + ty*4 + (i-4)));
#pragma unroll
        for (int jh = 0; jh < 2; jh++) {
            const int cbase = col0 + jh*64 + tx*4;
            float4 o;
            float* po = &o.x;
#pragma unroll
            for (int j = 0; j < 4; j++) {
                float v = acc[i][jh*4 + j] + bias[cbase + j];
                if (RELU) v = fmaxf(v, 0.f);
                po[j] = v;
            }
            *(float4*)&C[(size_t)r*N + cbase] = o;
        }
    }
}

// ---------------- fused residual add + LayerNorm (row = 1024) ----------------
__global__ __launch_bounds__(256)
void add_ln_kernel(const float* __restrict__ z, const float* __restrict__ res,
                   const float* __restrict__ g, const float* __restrict__ be,
                   float* __restrict__ out)
{
    const int row = blockIdx.x;
    const int tid = threadIdx.x;
    const float* zr = z   + (size_t)row*DM;
    const float* rr = res + (size_t)row*DM;

    float v[4];
    float s = 0.f, sq = 0.f;
#pragma unroll
    for (int i = 0; i < 4; i++) {
        const int c = tid + i*256;
        const float x = zr[c] + rr[c];
        v[i] = x; s += x; sq += x*x;
    }
#pragma unroll
    for (int o = 16; o; o >>= 1) {
        s  += __shfl_xor_sync(0xffffffffu, s,  o);
        sq += __shfl_xor_sync(0xffffffffu, sq, o);
    }
    __shared__ float ss[8], ssq[8];
    if ((tid & 31) == 0) { ss[tid >> 5] = s; ssq[tid >> 5] = sq; }
    __syncthreads();
    if (tid < 32) {
        s  = (tid < 8) ? ss[tid]  : 0.f;
        sq = (tid < 8) ? ssq[tid] : 0.f;
#pragma unroll
        for (int o = 4; o; o >>= 1) {
            s  += __shfl_xor_sync(0xffffffffu, s,  o);
            sq += __shfl_xor_sync(0xffffffffu, sq, o);
        }
        if (tid == 0) { ss[0] = s; ssq[0] = sq; }
    }
    __syncthreads();
    const float mean = ss[0] * (1.f/DM);
    const float var  = ssq[0] * (1.f/DM) - mean*mean;
    const float inv  = rsqrtf(var + 1e-5f);
    float* outr = out + (size_t)row*DM;
#pragma unroll
    for (int i = 0; i < 4; i++) {
        const int c = tid + i*256;
        outr[c] = (v[i] - mean)*inv*g[c] + be[c];
    }
}

// ---------------- flash attention --------------------------------------------
// grid: (S/64, H, B); block: 256 threads; dynamic smem 70144 B.
// Q/K/V/O layout: [B*S, H*64] row-major (head h occupies cols h*64..h*64+63).
__global__ __launch_bounds__(256)
void attn_kernel(const float* __restrict__ Qg, const float* __restrict__ Kg,
                 const float* __restrict__ Vg, float* __restrict__ Og,
                 int causal)
{
    extern __shared__ float sm[];
    float* Qs      = sm;               // [64][68]  Qs[r*68+d]
    float* Kts     = Qs  + 64*68;      // [64][68]  Kts[d*68+c] = K[c][d]
    float* Vs      = Kts + 64*68;      // [64][68]  Vs[c*68+d]
    float* Ss      = Vs  + 64*68;      // [64][68]
    float* alpha_s = Ss  + 64*68;      // [64]
    float* l_s     = alpha_s + 64;     // [64]

    const int qi  = blockIdx.x;
    const int h   = blockIdx.y;
    const int b   = blockIdx.z;
    const int tid = threadIdx.x;
    const int q0  = qi * 64;

    // load Q tile
#pragma unroll
    for (int t = 0; t < 4; t++) {
        const int i  = tid + t*256;           // 0..1023
        const int r  = i >> 4;
        const int dv = (i & 15) * 4;
        const float4 qv = *(const float4*)&Qg[(size_t)(b*SEQ + q0 + r)*DM + h*HD + dv];
        *(float4*)&Qs[r*68 + dv] = qv;
    }

    const int mr0  = (tid >> 4) * 4;   // 4x4 microtile rows
    const int mc0  = (tid & 15) * 4;   // 4x4 microtile cols
    const int rrow = tid >> 2;         // row-mapped softmax: 4 threads/row
    const int quad = tid & 3;

    float o[4][4];
#pragma unroll
    for (int i = 0; i < 4; i++)
#pragma unroll
        for (int j = 0; j < 4; j++) o[i][j] = 0.f;
    float mrow = -1e30f, lrow = 0.f;

    const int ntiles = causal ? (qi + 1) : (SEQ/64);
    for (int kt = 0; kt < ntiles; kt++) {
        const int k0 = kt * 64;
        // load K (transposed) and V
#pragma unroll
        for (int t = 0; t < 4; t++) {
            const int i  = tid + t*256;
            const int c  = i >> 4;
            const int dv = (i & 15) * 4;
            const size_t base = (size_t)(b*SEQ + k0 + c)*DM + h*HD + dv;
            const float4 kv = *(const float4*)&Kg[base];
            Kts[(dv+0)*68 + c] = kv.x;
            Kts[(dv+1)*68 + c] = kv.y;
            Kts[(dv+2)*68 + c] = kv.z;
            Kts[(dv+3)*68 + c] = kv.w;
            const float4 vv = *(const float4*)&Vg[base];
            *(float4*)&Vs[c*68 + dv] = vv;
        }
        __syncthreads();

        // S = Q K^T (4x4 microtile)
        float s4[4][4];
#pragma unroll
        for (int i = 0; i < 4; i++)
#pragma unroll
            for (int j = 0; j < 4; j++) s4[i][j] = 0.f;
#pragma unroll 16
        for (int kk = 0; kk < 64; kk++) {
            float a0 = Qs[(mr0+0)*68 + kk];
            float a1 = Qs[(mr0+1)*68 + kk];
            float a2 = Qs[(mr0+2)*68 + kk];
            float a3 = Qs[(mr0+3)*68 + kk];
            const float4 bbv = *(const float4*)&Kts[kk*68 + mc0];
            const float bb[4] = {bbv.x, bbv.y, bbv.z, bbv.w};
#pragma unroll
            for (int j = 0; j < 4; j++) {
                s4[0][j] = fmaf(a0, bb[j], s4[0][j]);
                s4[1][j] = fmaf(a1, bb[j], s4[1][j]);
                s4[2][j] = fmaf(a2, bb[j], s4[2][j]);
                s4[3][j] = fmaf(a3, bb[j], s4[3][j]);
            }
        }
        // scale + mask, write to Ss
#pragma unroll
        for (int i = 0; i < 4; i++) {
            const int grow = q0 + mr0 + i;
#pragma unroll
            for (int j = 0; j < 4; j++) {
                float sv = s4[i][j] * 0.125f;
                if (causal && (k0 + mc0 + j > grow)) sv = -1e9f;
                Ss[(mr0+i)*68 + mc0 + j] = sv;
            }
        }
        __syncthreads();

        // online softmax (4 threads/row)
        float sv[16];
        float smax = -1e30f;
#pragma unroll
        for (int j = 0; j < 16; j++) {
            sv[j] = Ss[rrow*68 + quad*16 + j];
            smax = fmaxf(smax, sv[j]);
        }
        smax = fmaxf(smax, __shfl_xor_sync(0xffffffffu, smax, 1));
        smax = fmaxf(smax, __shfl_xor_sync(0xffffffffu, smax, 2));
        const float mnew  = fmaxf(mrow, smax);
        const float alpha = __expf(mrow - mnew);
        float psum = 0.f;
#pragma unroll
        for (int j = 0; j < 16; j++) {
            const float p = __expf(sv[j] - mnew);
            psum += p;
            Ss[rrow*68 + quad*16 + j] = p;
        }
        psum += __shfl_xor_sync(0xffffffffu, psum, 1);
        psum += __shfl_xor_sync(0xffffffffu, psum, 2);
        lrow = lrow*alpha + psum;
        mrow = mnew;
        if (quad == 0) alpha_s[rrow] = alpha;
        __syncthreads();

        // O = O*alpha + P @ V (4x4 microtile)
#pragma unroll
        for (int i = 0; i < 4; i++) {
            const float al = alpha_s[mr0+i];
#pragma unroll
            for (int j = 0; j < 4; j++) o[i][j] *= al;
        }
#pragma unroll 8
        for (int c = 0; c < 64; c++) {
            const float p0 = Ss[(mr0+0)*68 + c];
            const float p1 = Ss[(mr0+1)*68 + c];
            const float p2 = Ss[(mr0+2)*68 + c];
            const float p3 = Ss[(mr0+3)*68 + c];
            const float4 vvv = *(const float4*)&Vs[c*68 + mc0];
            const float vv[4] = {vvv.x, vvv.y, vvv.z, vvv.w};
#pragma unroll
            for (int j = 0; j < 4; j++) {
                o[0][j] = fmaf(p0, vv[j], o[0][j]);
                o[1][j] = fmaf(p1, vv[j], o[1][j]);
                o[2][j] = fmaf(p2, vv[j], o[2][j]);
                o[3][j] = fmaf(p3, vv[j], o[3][j]);
            }
        }
        __syncthreads();
    }

    if (quad == 0) l_s[rrow] = lrow;
    __syncthreads();

#pragma unroll
    for (int i = 0; i < 4; i++) {
        const float inv = 1.f / l_s[mr0+i];
        float4 ov;
        ov.x = o[i][0]*inv; ov.y = o[i][1]*inv; ov.z = o[i][2]*inv; ov.w = o[i][3]*inv;
        *(float4*)&Og[(size_t)(b*SEQ + q0 + mr0 + i)*DM + h*HD + mc0] = ov;
    }
}

// ---------------- launch ------------------------------------------------------
extern "C" void kernel_launch(void* const* d_in, const int* in_sizes, int n_in,
                              void* d_out, int out_size)
{
    (void)in_sizes; (void)n_in; (void)out_size;
    const float* dec = (const float*)d_in[0];
    const float* enc = (const float*)d_in[1];
    // d_in[2], d_in[3]: masks (structurally causal / all-ones; handled by flag)
    const float* wq1 = (const float*)d_in[4];
    const float* bq1 = (const float*)d_in[5];
    const float* wk1 = (const float*)d_in[6];
    const float* bk1 = (const float*)d_in[7];
    const float* wv1 = (const float*)d_in[8];
    const float* bv1 = (const float*)d_in[9];
    const float* zw1 = (const float*)d_in[10];
    const float* zb1 = (const float*)d_in[11];
    const float* g1  = (const float*)d_in[12];
    const float* be1 = (const float*)d_in[13];
    const float* wq2 = (const float*)d_in[14];
    const float* bq2 = (const float*)d_in[15];
    const float* wk2 = (const float*)d_in[16];
    const float* bk2 = (const float*)d_in[17];
    const float* wv2 = (const float*)d_in[18];
    const float* bv2 = (const float*)d_in[19];
    const float* zw2 = (const float*)d_in[20];
    const float* zb2 = (const float*)d_in[21];
    const float* g2  = (const float*)d_in[22];
    const float* be2 = (const float*)d_in[23];
    const float* fw1 = (const float*)d_in[24];
    const float* fb1 = (const float*)d_in[25];
    const float* fw2 = (const float*)d_in[26];
    const float* fb2 = (const float*)d_in[27];
    const float* g3  = (const float*)d_in[28];
    const float* be3 = (const float*)d_in[29];
    float* out = (float*)d_out;

    float *qp, *kp, *vp, *aop, *zp, *o1p, *o2p, *ffp;
    cudaGetSymbolAddress((void**)&qp,  g_q);
    cudaGetSymbolAddress((void**)&kp,  g_k);
    cudaGetSymbolAddress((void**)&vp,  g_v);
    cudaGetSymbolAddress((void**)&aop, g_ao);
    cudaGetSymbolAddress((void**)&zp,  g_z);
    cudaGetSymbolAddress((void**)&o1p, g_o1);
    cudaGetSymbolAddress((void**)&o2p, g_o2);
    cudaGetSymbolAddress((void**)&ffp, g_ff);

    const int ATTN_SMEM = (4*64*68 + 128) * 4;  // 70144 B
    cudaFuncSetAttribute(attn_kernel, cudaFuncAttributeMaxDynamicSharedMemorySize, ATTN_SMEM);

    const dim3 gD (DM/128,  TOK/128);   // (8, 32)  N=1024
    const dim3 gFF(FFD/128, TOK/128);   // (32, 32) N=4096
    const dim3 gA (SEQ/64, NH, BB);     // (16, 16, 4)

    // ---- self-attention block ----
    gemm_kernel<false><<<gD, 256>>>(dec, wq1, bq1, qp, TOK, DM, DM);
    gemm_kernel<false><<<gD, 256>>>(dec, wk1, bk1, kp, TOK, DM, DM);
    gemm_kernel<false><<<gD, 256>>>(dec, wv1, bv1, vp, TOK, DM, DM);
    attn_kernel<<<gA, 256, ATTN_SMEM>>>(qp, kp, vp, aop, 1);
    gemm_kernel<false><<<gD, 256>>>(aop, zw1, zb1, zp, TOK, DM, DM);
    add_ln_kernel<<<TOK, 256>>>(zp, dec, g1, be1, o1p);

    // ---- cross-attention block ----
    gemm_kernel<false><<<gD, 256>>>(o1p, wq2, bq2, qp, TOK, DM, DM);
    gemm_kernel<false><<<gD, 256>>>(enc, wk2, bk2, kp, TOK, DM, DM);
    gemm_kernel<false><<<gD, 256>>>(enc, wv2, bv2, vp, TOK, DM, DM);
    attn_kernel<<<gA, 256, ATTN_SMEM>>>(qp, kp, vp, aop, 0);
    gemm_kernel<false><<<gD, 256>>>(aop, zw2, zb2, zp, TOK, DM, DM);
    add_ln_kernel<<<TOK, 256>>>(zp, o1p, g2, be2, o2p);

    // ---- feed-forward block ----
    gemm_kernel<true ><<<gFF, 256>>>(o2p, fw1, fb1, ffp, TOK, FFD, DM);
    gemm_kernel<false><<<gD, 256>>>(ffp, fw2, fb2, zp, TOK, DM, FFD);
    add_ln_kernel<<<TOK, 256>>>(zp, o2p, g3, be3, out);
}

// round 5
// speedup vs baseline: 1.6359x; 1.6359x over previous
#include <cuda_runtime.h>
#include <cuda_bf16.h>
#include <math.h>
#include <stdint.h>

// Problem constants
#define BB   4
#define SEQ  1024
#define DM   1024
#define NH   16
#define HD   64
#define FFD  4096
#define TOK  (BB*SEQ)   // 4096
#define MEG  (1024*1024)

typedef __nv_bfloat16 bf16;

// ---------------- scratch (device globals: no allocs allowed) ----------------
__device__ float g_q  [TOK*DM];
__device__ float g_k  [TOK*DM];
__device__ float g_v  [TOK*DM];
__device__ float g_z  [TOK*DM];
__device__ float g_o1 [TOK*DM];
__device__ float g_o2 [TOK*DM];
__device__ bf16  g_dech[TOK*DM], g_decl[TOK*DM];
__device__ bf16  g_ench[TOK*DM], g_encl[TOK*DM];
__device__ bf16  g_aoh [TOK*DM], g_aol [TOK*DM];
__device__ bf16  g_o1h [TOK*DM], g_o1l [TOK*DM];
__device__ bf16  g_o2h [TOK*DM], g_o2l [TOK*DM];
__device__ bf16  g_ffh [TOK*FFD], g_ffl[TOK*FFD];
__device__ bf16  g_wh[16*MEG], g_wl[16*MEG];

// ==================== low-level helpers (sm_100 baseline ISA) =================
__device__ __forceinline__ uint32_t smem_u32(const void* p) {
    uint32_t a;
    asm("{ .reg .u64 t; cvta.to.shared.u64 t, %1; cvt.u32.u64 %0, t; }" : "=r"(a) : "l"(p));
    return a;
}
__device__ __forceinline__ void cpa16(uint32_t s, const void* g) {
    asm volatile("cp.async.cg.shared.global [%0], [%1], 16;" :: "r"(s), "l"(g));
}
#define CPA_COMMIT() asm volatile("cp.async.commit_group;" ::: "memory")
#define CPA_WAIT2()  asm volatile("cp.async.wait_group 2;"  ::: "memory")

#define LDSM4(r, a) \
    asm volatile("ldmatrix.sync.aligned.m8n8.x4.shared.b16 {%0,%1,%2,%3}, [%4];" \
        : "=r"((r)[0]), "=r"((r)[1]), "=r"((r)[2]), "=r"((r)[3]) : "r"(a))

#define MMA16816(c, a, b0, b1) \
    asm volatile("mma.sync.aligned.m16n8k16.row.col.f32.bf16.bf16.f32 " \
        "{%0,%1,%2,%3},{%4,%5,%6,%7},{%8,%9},{%0,%1,%2,%3};" \
        : "+f"((c)[0]), "+f"((c)[1]), "+f"((c)[2]), "+f"((c)[3]) \
        : "r"((a)[0]), "r"((a)[1]), "r"((a)[2]), "r"((a)[3]), "r"(b0), "r"(b1))

__device__ __forceinline__ void split1(float x, bf16& h, bf16& l) {
    h = __float2bfloat16_rn(x);
    l = __float2bfloat16_rn(x - __bfloat162float(h));
}

// ============ weight transpose + bf16 split: W[K,N] -> Th/Tl[N,K] =============
__global__ __launch_bounds__(256)
void wsplit_t(const float* __restrict__ W, bf16* __restrict__ Th,
              bf16* __restrict__ Tl, int K, int N)
{
    __shared__ float t[32][33];
    const int n0 = blockIdx.x * 32, k0 = blockIdx.y * 32;
    const int tx = threadIdx.x, ty = threadIdx.y;   // 32 x 8
#pragma unroll
    for (int i = 0; i < 4; i++)
        t[ty + i*8][tx] = W[(size_t)(k0 + ty + i*8) * N + n0 + tx];
    __syncthreads();
#pragma unroll
    for (int i = 0; i < 4; i++) {
        const int r = ty + i*8;
        const float v = t[tx][r];
        bf16 h, l; split1(v, h, l);
        Th[(size_t)(n0 + r) * K + k0 + tx] = h;
        Tl[(size_t)(n0 + r) * K + k0 + tx] = l;
    }
}

// ============ activation split: X fp32 [n] -> Xh, Xl bf16 =====================
__global__ __launch_bounds__(256)
void split_act(const float* __restrict__ X, bf16* __restrict__ Xh,
               bf16* __restrict__ Xl, int n4)
{
    const int i = blockIdx.x * 256 + threadIdx.x;
    if (i >= n4) return;
    const float4 v = ((const float4*)X)[i];
    bf16 h0,l0,h1,l1,h2,l2,h3,l3;
    split1(v.x,h0,l0); split1(v.y,h1,l1); split1(v.z,h2,l2); split1(v.w,h3,l3);
    __nv_bfloat162 ph[2] = {{h0,h1},{h2,h3}};
    __nv_bfloat162 pl[2] = {{l0,l1},{l2,l3}};
    ((uint2*)Xh)[i] = *(uint2*)ph;
    ((uint2*)Xl)[i] = *(uint2*)pl;
}

// ========== mma.sync GEMM: C[M,N] = A @ W + bias ==============================
// A: bf16 hi/lo [M,K] k-contig.  B: bf16 hi/lo [N,K] k-contig (pre-transposed).
// C = Ah*Bh + Ah*Bl + Al*Bh  (bf16x3 split, fp32 accum).
// CTA 128x128, BK=32, 8 warps (warp tile 64x32), 4-stage cp.async pipeline.
// OUT=0: fp32 C + bias.  OUT=1: relu(C+bias) split to bf16 hi/lo (Ch/Cl).
#define GEMM_SMEM (4*32768)   // 131072

template<int OUT>
__global__ __launch_bounds__(256)
void gemm_ts(const bf16* __restrict__ Ah, const bf16* __restrict__ Al,
             const bf16* __restrict__ Bh, const bf16* __restrict__ Bl,
             const float* __restrict__ bias, float* __restrict__ C,
             bf16* __restrict__ Ch, bf16* __restrict__ Cl, int N, int K)
{
    extern __shared__ char smraw[];
    const uint32_t sb0 = smem_u32(smraw);          // 4 stages x 32768 B
    const int tid  = threadIdx.x;
    const int lane = tid & 31;
    const int w    = tid >> 5;
    const int m0   = blockIdx.y * 128;
    const int n0   = blockIdx.x * 128;
    const int wm   = (w >> 2) * 64;
    const int wn   = (w & 3) * 32;
    const int r15  = lane & 15;
    const int kh   = lane >> 4;

    // precompute swizzled ldmatrix byte offsets (within a tile)
    uint32_t aoff[4][2], boff[2][2];
#pragma unroll
    for (int bm = 0; bm < 4; bm++) {
        const int row = wm + bm*16 + r15;
        const int sw  = (row >> 1) & 3;
#pragma unroll
        for (int ks = 0; ks < 2; ks++)
            aoff[bm][ks] = row*64 + (((ks*2 + kh) ^ sw) << 4);
    }
#pragma unroll
    for (int bp = 0; bp < 2; bp++) {
        const int row = wn + bp*16 + r15;
        const int sw  = (row >> 1) & 3;
#pragma unroll
        for (int ks = 0; ks < 2; ks++)
            boff[bp][ks] = row*64 + (((ks*2 + kh) ^ sw) << 4);
    }

    // stage loader: 4 tiles x 512 x 16B chunks; tile order Ah,Al,Bh,Bl
    const bf16* gbase[4] = {Ah + (size_t)m0*K, Al + (size_t)m0*K,
                            Bh + (size_t)n0*K, Bl + (size_t)n0*K};
    auto load_stage = [&](int s, int k0) {
        const uint32_t stb = sb0 + s*32768;
#pragma unroll
        for (int i = 0; i < 8; i++) {
            const int tile = i >> 1;
            const int idx  = ((i & 1) << 8) + tid;      // 0..511
            const int row  = idx >> 2;
            const int c    = idx & 3;
            const int sc   = c ^ ((row >> 1) & 3);
            cpa16(stb + tile*8192 + row*64 + sc*16,
                  gbase[tile] + (size_t)row*K + k0 + c*8);
        }
    };

    float acc[4][4][4];
#pragma unroll
    for (int bm = 0; bm < 4; bm++)
#pragma unroll
        for (int bn = 0; bn < 4; bn++)
#pragma unroll
            for (int j = 0; j < 4; j++) acc[bm][bn][j] = 0.f;

    const int CH = K >> 5;
    load_stage(0, 0);  CPA_COMMIT();
    load_stage(1, 32); CPA_COMMIT();
    load_stage(2, 64); CPA_COMMIT();

    for (int c = 0; c < CH; ++c) {
        CPA_WAIT2();
        __syncthreads();
        // prefetch chunk c+3 into the stage that chunk c-1 vacated
        if (c + 3 < CH) load_stage((c + 3) & 3, (c + 3) * 32);
        CPA_COMMIT();

        const uint32_t stb = sb0 + (c & 3)*32768;
#pragma unroll
        for (int ks = 0; ks < 2; ks++) {
            uint32_t ah[4][4], al[4][4], bh[2][4], bl[2][4];
#pragma unroll
            for (int bm = 0; bm < 4; bm++) {
                LDSM4(ah[bm], stb +        aoff[bm][ks]);
                LDSM4(al[bm], stb + 8192 + aoff[bm][ks]);
            }
#pragma unroll
            for (int bp = 0; bp < 2; bp++) {
                LDSM4(bh[bp], stb + 16384 + boff[bp][ks]);
                LDSM4(bl[bp], stb + 24576 + boff[bp][ks]);
            }
#pragma unroll
            for (int bm = 0; bm < 4; bm++)
#pragma unroll
                for (int bn = 0; bn < 4; bn++) {
                    const int bp = bn >> 1, sel = bn & 1;
                    MMA16816(acc[bm][bn], ah[bm], bh[bp][sel], bh[bp][sel+2]);
                    MMA16816(acc[bm][bn], ah[bm], bl[bp][sel], bl[bp][sel+2]);
                    MMA16816(acc[bm][bn], al[bm], bh[bp][sel], bh[bp][sel+2]);
                }
        }
    }

    // epilogue
    const int er = lane >> 2;
    const int ec = (lane & 3) * 2;
#pragma unroll
    for (int bm = 0; bm < 4; bm++)
#pragma unroll
        for (int bn = 0; bn < 4; bn++) {
            const int col = n0 + wn + bn*8 + ec;
            const float b0 = bias[col], b1 = bias[col+1];
#pragma unroll
            for (int half = 0; half < 2; half++) {
                const int r = m0 + wm + bm*16 + er + half*8;
                float v0 = acc[bm][bn][half*2+0] + b0;
                float v1 = acc[bm][bn][half*2+1] + b1;
                if (OUT == 0) {
                    float2 o = {v0, v1};
                    *(float2*)&C[(size_t)r*N + col] = o;
                } else {
                    v0 = fmaxf(v0, 0.f); v1 = fmaxf(v1, 0.f);
                    bf16 h0,l0,h1,l1;
                    split1(v0,h0,l0); split1(v1,h1,l1);
                    __nv_bfloat162 ph = {h0,h1}, pl = {l0,l1};
                    *(__nv_bfloat162*)&Ch[(size_t)r*N + col] = ph;
                    *(__nv_bfloat162*)&Cl[(size_t)r*N + col] = pl;
                }
            }
        }
}

// ---------------- fused residual add + LayerNorm (row = 1024) ----------------
template<bool SPLIT>
__global__ __launch_bounds__(256)
void add_ln_kernel(const float* __restrict__ z, const float* __restrict__ res,
                   const float* __restrict__ g, const float* __restrict__ be,
                   float* __restrict__ out, bf16* __restrict__ oh, bf16* __restrict__ ol)
{
    const int row = blockIdx.x;
    const int tid = threadIdx.x;
    const float* zr = z   + (size_t)row*DM;
    const float* rr = res + (size_t)row*DM;

    float v[4];
    float s = 0.f, sq = 0.f;
#pragma unroll
    for (int i = 0; i < 4; i++) {
        const int c = tid + i*256;
        const float x = zr[c] + rr[c];
        v[i] = x; s += x; sq += x*x;
    }
#pragma unroll
    for (int o = 16; o; o >>= 1) {
        s  += __shfl_xor_sync(0xffffffffu, s,  o);
        sq += __shfl_xor_sync(0xffffffffu, sq, o);
    }
    __shared__ float ss[8], ssq[8];
    if ((tid & 31) == 0) { ss[tid >> 5] = s; ssq[tid >> 5] = sq; }
    __syncthreads();
    if (tid < 32) {
        s  = (tid < 8) ? ss[tid]  : 0.f;
        sq = (tid < 8) ? ssq[tid] : 0.f;
#pragma unroll
        for (int o = 4; o; o >>= 1) {
            s  += __shfl_xor_sync(0xffffffffu, s,  o);
            sq += __shfl_xor_sync(0xffffffffu, sq, o);
        }
        if (tid == 0) { ss[0] = s; ssq[0] = sq; }
    }
    __syncthreads();
    const float mean = ss[0] * (1.f/DM);
    const float var  = ssq[0] * (1.f/DM) - mean*mean;
    const float inv  = rsqrtf(var + 1e-5f);
#pragma unroll
    for (int i = 0; i < 4; i++) {
        const int c = tid + i*256;
        const float y = (v[i] - mean)*inv*g[c] + be[c];
        out[(size_t)row*DM + c] = y;
        if (SPLIT) {
            bf16 h, l; split1(y, h, l);
            oh[(size_t)row*DM + c] = h;
            ol[(size_t)row*DM + c] = l;
        }
    }
}

// ---------------- flash attention (fp32; epilogue emits bf16 hi/lo) -----------
__global__ __launch_bounds__(256)
void attn_kernel(const float* __restrict__ Qg, const float* __restrict__ Kg,
                 const float* __restrict__ Vg, bf16* __restrict__ Oh,
                 bf16* __restrict__ Ol, int causal)
{
    extern __shared__ float sm[];
    float* Qs      = sm;
    float* Kts     = Qs  + 64*68;
    float* Vs      = Kts + 64*68;
    float* Ss      = Vs  + 64*68;
    float* alpha_s = Ss  + 64*68;
    float* l_s     = alpha_s + 64;

    const int qi  = blockIdx.x;
    const int h   = blockIdx.y;
    const int b   = blockIdx.z;
    const int tid = threadIdx.x;
    const int q0  = qi * 64;

#pragma unroll
    for (int t = 0; t < 4; t++) {
        const int i  = tid + t*256;
        const int r  = i >> 4;
        const int dv = (i & 15) * 4;
        const float4 qv = *(const float4*)&Qg[(size_t)(b*SEQ + q0 + r)*DM + h*HD + dv];
        *(float4*)&Qs[r*68 + dv] = qv;
    }

    const int mr0  = (tid >> 4) * 4;
    const int mc0  = (tid & 15) * 4;
    const int rrow = tid >> 2;
    const int quad = tid & 3;

    float o[4][4];
#pragma unroll
    for (int i = 0; i < 4; i++)
#pragma unroll
        for (int j = 0; j < 4; j++) o[i][j] = 0.f;
    float mrow = -1e30f, lrow = 0.f;

    const int ntiles = causal ? (qi + 1) : (SEQ/64);
    for (int kt = 0; kt < ntiles; kt++) {
        const int k0 = kt * 64;
#pragma unroll
        for (int t = 0; t < 4; t++) {
            const int i  = tid + t*256;
            const int c  = i >> 4;
            const int dv = (i & 15) * 4;
            const size_t base = (size_t)(b*SEQ + k0 + c)*DM + h*HD + dv;
            const float4 kv = *(const float4*)&Kg[base];
            Kts[(dv+0)*68 + c] = kv.x;
            Kts[(dv+1)*68 + c] = kv.y;
            Kts[(dv+2)*68 + c] = kv.z;
            Kts[(dv+3)*68 + c] = kv.w;
            const float4 vv = *(const float4*)&Vg[base];
            *(float4*)&Vs[c*68 + dv] = vv;
        }
        __syncthreads();

        float s4[4][4];
#pragma unroll
        for (int i = 0; i < 4; i++)
#pragma unroll
            for (int j = 0; j < 4; j++) s4[i][j] = 0.f;
#pragma unroll 16
        for (int kk = 0; kk < 64; kk++) {
            float a0 = Qs[(mr0+0)*68 + kk];
            float a1 = Qs[(mr0+1)*68 + kk];
            float a2 = Qs[(mr0+2)*68 + kk];
            float a3 = Qs[(mr0+3)*68 + kk];
            const float4 bbv = *(const float4*)&Kts[kk*68 + mc0];
            const float bb[4] = {bbv.x, bbv.y, bbv.z, bbv.w};
#pragma unroll
            for (int j = 0; j < 4; j++) {
                s4[0][j] = fmaf(a0, bb[j], s4[0][j]);
                s4[1][j] = fmaf(a1, bb[j], s4[1][j]);
                s4[2][j] = fmaf(a2, bb[j], s4[2][j]);
                s4[3][j] = fmaf(a3, bb[j], s4[3][j]);
            }
        }
#pragma unroll
        for (int i = 0; i < 4; i++) {
            const int grow = q0 + mr0 + i;
#pragma unroll
            for (int j = 0; j < 4; j++) {
                float sv = s4[i][j] * 0.125f;
                if (causal && (k0 + mc0 + j > grow)) sv = -1e9f;
                Ss[(mr0+i)*68 + mc0 + j] = sv;
            }
        }
        __syncthreads();

        float sv[16];
        float smax = -1e30f;
#pragma unroll
        for (int j = 0; j < 16; j++) {
            sv[j] = Ss[rrow*68 + quad*16 + j];
            smax = fmaxf(smax, sv[j]);
        }
        smax = fmaxf(smax, __shfl_xor_sync(0xffffffffu, smax, 1));
        smax = fmaxf(smax, __shfl_xor_sync(0xffffffffu, smax, 2));
        const float mnew  = fmaxf(mrow, smax);
        const float alpha = __expf(mrow - mnew);
        float psum = 0.f;
#pragma unroll
        for (int j = 0; j < 16; j++) {
            const float p = __expf(sv[j] - mnew);
            psum += p;
            Ss[rrow*68 + quad*16 + j] = p;
        }
        psum += __shfl_xor_sync(0xffffffffu, psum, 1);
        psum += __shfl_xor_sync(0xffffffffu, psum, 2);
        lrow = lrow*alpha + psum;
        mrow = mnew;
        if (quad == 0) alpha_s[rrow] = alpha;
        __syncthreads();

#pragma unroll
        for (int i = 0; i < 4; i++) {
            const float al = alpha_s[mr0+i];
#pragma unroll
            for (int j = 0; j < 4; j++) o[i][j] *= al;
        }
#pragma unroll 8
        for (int c = 0; c < 64; c++) {
            const float p0 = Ss[(mr0+0)*68 + c];
            const float p1 = Ss[(mr0+1)*68 + c];
            const float p2 = Ss[(mr0+2)*68 + c];
            const float p3 = Ss[(mr0+3)*68 + c];
            const float4 vvv = *(const float4*)&Vs[c*68 + mc0];
            const float vv[4] = {vvv.x, vvv.y, vvv.z, vvv.w};
#pragma unroll
            for (int j = 0; j < 4; j++) {
                o[0][j] = fmaf(p0, vv[j], o[0][j]);
                o[1][j] = fmaf(p1, vv[j], o[1][j]);
                o[2][j] = fmaf(p2, vv[j], o[2][j]);
                o[3][j] = fmaf(p3, vv[j], o[3][j]);
            }
        }
        __syncthreads();
    }

    if (quad == 0) l_s[rrow] = lrow;
    __syncthreads();

#pragma unroll
    for (int i = 0; i < 4; i++) {
        const float inv = 1.f / l_s[mr0+i];
        bf16 h0,l0,h1,l1,h2,l2,h3,l3;
        split1(o[i][0]*inv, h0, l0);
        split1(o[i][1]*inv, h1, l1);
        split1(o[i][2]*inv, h2, l2);
        split1(o[i][3]*inv, h3, l3);
        __nv_bfloat162 ph[2] = {{h0,h1},{h2,h3}};
        __nv_bfloat162 pl[2] = {{l0,l1},{l2,l3}};
        const size_t base = (size_t)(b*SEQ + q0 + mr0 + i)*DM + h*HD + mc0;
        *(uint2*)&Oh[base] = *(uint2*)ph;
        *(uint2*)&Ol[base] = *(uint2*)pl;
    }
}

// ---------------- launch ------------------------------------------------------
extern "C" void kernel_launch(void* const* d_in, const int* in_sizes, int n_in,
                              void* d_out, int out_size)
{
    (void)in_sizes; (void)n_in; (void)out_size;
    const float* dec = (const float*)d_in[0];
    const float* enc = (const float*)d_in[1];
    const float* bq1 = (const float*)d_in[5];
    const float* bk1 = (const float*)d_in[7];
    const float* bv1 = (const float*)d_in[9];
    const float* zb1 = (const float*)d_in[11];
    const float* g1  = (const float*)d_in[12];
    const float* be1 = (const float*)d_in[13];
    const float* bq2 = (const float*)d_in[15];
    const float* bk2 = (const float*)d_in[17];
    const float* bv2 = (const float*)d_in[19];
    const float* zb2 = (const float*)d_in[21];
    const float* g2  = (const float*)d_in[22];
    const float* be2 = (const float*)d_in[23];
    const float* fb1 = (const float*)d_in[25];
    const float* fb2 = (const float*)d_in[27];
    const float* g3  = (const float*)d_in[28];
    const float* be3 = (const float*)d_in[29];
    float* out = (float*)d_out;

    float *qp, *kp, *vp, *zp, *o1p, *o2p;
    bf16 *dech,*decl,*ench,*encl,*aoh,*aol,*o1h,*o1l,*o2h,*o2l,*ffh,*ffl,*whp,*wlp;
    cudaGetSymbolAddress((void**)&qp,  g_q);
    cudaGetSymbolAddress((void**)&kp,  g_k);
    cudaGetSymbolAddress((void**)&vp,  g_v);
    cudaGetSymbolAddress((void**)&zp,  g_z);
    cudaGetSymbolAddress((void**)&o1p, g_o1);
    cudaGetSymbolAddress((void**)&o2p, g_o2);
    cudaGetSymbolAddress((void**)&dech, g_dech); cudaGetSymbolAddress((void**)&decl, g_decl);
    cudaGetSymbolAddress((void**)&ench, g_ench); cudaGetSymbolAddress((void**)&encl, g_encl);
    cudaGetSymbolAddress((void**)&aoh,  g_aoh);  cudaGetSymbolAddress((void**)&aol,  g_aol);
    cudaGetSymbolAddress((void**)&o1h,  g_o1h);  cudaGetSymbolAddress((void**)&o1l,  g_o1l);
    cudaGetSymbolAddress((void**)&o2h,  g_o2h);  cudaGetSymbolAddress((void**)&o2l,  g_o2l);
    cudaGetSymbolAddress((void**)&ffh,  g_ffh);  cudaGetSymbolAddress((void**)&ffl,  g_ffl);
    cudaGetSymbolAddress((void**)&whp,  g_wh);   cudaGetSymbolAddress((void**)&wlp,  g_wl);

    const int ATTN_SMEM = (4*64*68 + 128) * 4;
    cudaFuncSetAttribute(attn_kernel, cudaFuncAttributeMaxDynamicSharedMemorySize, ATTN_SMEM);
    cudaFuncSetAttribute(gemm_ts<0>, cudaFuncAttributeMaxDynamicSharedMemorySize, GEMM_SMEM);
    cudaFuncSetAttribute(gemm_ts<1>, cudaFuncAttributeMaxDynamicSharedMemorySize, GEMM_SMEM);

    // ---- weight transpose + split ----
    {
        const dim3 b(32, 8);
        wsplit_t<<<dim3(32, 32),  b>>>((const float*)d_in[4],  whp + 0*MEG,  wlp + 0*MEG,  DM,  DM);
        wsplit_t<<<dim3(32, 32),  b>>>((const float*)d_in[6],  whp + 1*MEG,  wlp + 1*MEG,  DM,  DM);
        wsplit_t<<<dim3(32, 32),  b>>>((const float*)d_in[8],  whp + 2*MEG,  wlp + 2*MEG,  DM,  DM);
        wsplit_t<<<dim3(32, 32),  b>>>((const float*)d_in[10], whp + 3*MEG,  wlp + 3*MEG,  DM,  DM);
        wsplit_t<<<dim3(32, 32),  b>>>((const float*)d_in[14], whp + 4*MEG,  wlp + 4*MEG,  DM,  DM);
        wsplit_t<<<dim3(32, 32),  b>>>((const float*)d_in[16], whp + 5*MEG,  wlp + 5*MEG,  DM,  DM);
        wsplit_t<<<dim3(32, 32),  b>>>((const float*)d_in[18], whp + 6*MEG,  wlp + 6*MEG,  DM,  DM);
        wsplit_t<<<dim3(32, 32),  b>>>((const float*)d_in[20], whp + 7*MEG,  wlp + 7*MEG,  DM,  DM);
        wsplit_t<<<dim3(128, 32), b>>>((const float*)d_in[24], whp + 8*MEG,  wlp + 8*MEG,  DM,  FFD);
        wsplit_t<<<dim3(32, 128), b>>>((const float*)d_in[26], whp + 12*MEG, wlp + 12*MEG, FFD, DM);
    }
    // ---- input splits ----
    split_act<<<TOK*DM/1024, 256>>>(dec, dech, decl, TOK*DM/4);
    split_act<<<TOK*DM/1024, 256>>>(enc, ench, encl, TOK*DM/4);

    const dim3 gD (8, 32);     // N=1024
    const dim3 gFF(32, 32);    // N=4096
    const dim3 gA (SEQ/64, NH, BB);

    // ---- self-attention block ----
    gemm_ts<0><<<gD, 256, GEMM_SMEM>>>(dech, decl, whp + 0*MEG, wlp + 0*MEG, bq1, qp, 0, 0, DM, DM);
    gemm_ts<0><<<gD, 256, GEMM_SMEM>>>(dech, decl, whp + 1*MEG, wlp + 1*MEG, bk1, kp, 0, 0, DM, DM);
    gemm_ts<0><<<gD, 256, GEMM_SMEM>>>(dech, decl, whp + 2*MEG, wlp + 2*MEG, bv1, vp, 0, 0, DM, DM);
    attn_kernel<<<gA, 256, ATTN_SMEM>>>(qp, kp, vp, aoh, aol, 1);
    gemm_ts<0><<<gD, 256, GEMM_SMEM>>>(aoh, aol, whp + 3*MEG, wlp + 3*MEG, zb1, zp, 0, 0, DM, DM);
    add_ln_kernel<true><<<TOK, 256>>>(zp, dec, g1, be1, o1p, o1h, o1l);

    // ---- cross-attention block ----
    gemm_ts<0><<<gD, 256, GEMM_SMEM>>>(o1h, o1l, whp + 4*MEG, wlp + 4*MEG, bq2, qp, 0, 0, DM, DM);
    gemm_ts<0><<<gD, 256, GEMM_SMEM>>>(ench, encl, whp + 5*MEG, wlp + 5*MEG, bk2, kp, 0, 0, DM, DM);
    gemm_ts<0><<<gD, 256, GEMM_SMEM>>>(ench, encl, whp + 6*MEG, wlp + 6*MEG, bv2, vp, 0, 0, DM, DM);
    attn_kernel<<<gA, 256, ATTN_SMEM>>>(qp, kp, vp, aoh, aol, 0);
    gemm_ts<0><<<gD, 256, GEMM_SMEM>>>(aoh, aol, whp + 7*MEG, wlp + 7*MEG, zb2, zp, 0, 0, DM, DM);
    add_ln_kernel<true><<<TOK, 256>>>(zp, o1p, g2, be2, o2p, o2h, o2l);

    // ---- feed-forward block ----
    gemm_ts<1><<<gFF, 256, GEMM_SMEM>>>(o2h, o2l, whp + 8*MEG,  wlp + 8*MEG,  fb1, 0, ffh, ffl, FFD, DM);
    gemm_ts<0><<<gD,  256, GEMM_SMEM>>>(ffh, ffl, whp + 12*MEG, wlp + 12*MEG, fb2, zp, 0, 0, DM, FFD);
    add_ln_kernel<false><<<TOK, 256>>>(zp, o2p, g3, be3, out, 0, 0);
}

// round 6
// speedup vs baseline: 2.1536x; 1.3165x over previous
#include <cuda_runtime.h>
#include <cuda_bf16.h>
#include <math.h>
#include <stdint.h>

// Problem constants
#define BB   4
#define SEQ  1024
#define DM   1024
#define NH   16
#define HD   64
#define FFD  4096
#define TOK  (BB*SEQ)   // 4096
#define MEG  (1024*1024)

typedef __nv_bfloat16 bf16;

// ---------------- scratch (device globals: no allocs allowed) ----------------
__device__ float g_z  [TOK*DM];
__device__ float g_o1 [TOK*DM];
__device__ float g_o2 [TOK*DM];
__device__ bf16  g_dech[TOK*DM], g_decl[TOK*DM];
__device__ bf16  g_ench[TOK*DM], g_encl[TOK*DM];
__device__ bf16  g_qh [TOK*DM], g_ql [TOK*DM];
__device__ bf16  g_kh [TOK*DM], g_kl [TOK*DM];
__device__ bf16  g_vh [TOK*DM], g_vl [TOK*DM];
__device__ bf16  g_aoh [TOK*DM], g_aol [TOK*DM];
__device__ bf16  g_o1h [TOK*DM], g_o1l [TOK*DM];
__device__ bf16  g_o2h [TOK*DM], g_o2l [TOK*DM];
__device__ bf16  g_ffh [TOK*FFD], g_ffl[TOK*FFD];
__device__ bf16  g_wh[16*MEG], g_wl[16*MEG];

// ==================== low-level helpers (sm_100 baseline ISA) =================
__device__ __forceinline__ uint32_t smem_u32(const void* p) {
    uint32_t a;
    asm("{ .reg .u64 t; cvta.to.shared.u64 t, %1; cvt.u32.u64 %0, t; }" : "=r"(a) : "l"(p));
    return a;
}
__device__ __forceinline__ void cpa16(uint32_t s, const void* g) {
    asm volatile("cp.async.cg.shared.global [%0], [%1], 16;" :: "r"(s), "l"(g));
}
#define CPA_COMMIT() asm volatile("cp.async.commit_group;" ::: "memory")
#define CPA_WAIT1()  asm volatile("cp.async.wait_group 1;"  ::: "memory")
#define CPA_WAIT2()  asm volatile("cp.async.wait_group 2;"  ::: "memory")

#define LDSM4(r, a) \
    asm volatile("ldmatrix.sync.aligned.m8n8.x4.shared.b16 {%0,%1,%2,%3}, [%4];" \
        : "=r"((r)[0]), "=r"((r)[1]), "=r"((r)[2]), "=r"((r)[3]) : "r"(a))
#define LDSM4T(r, a) \
    asm volatile("ldmatrix.sync.aligned.m8n8.x4.trans.shared.b16 {%0,%1,%2,%3}, [%4];" \
        : "=r"((r)[0]), "=r"((r)[1]), "=r"((r)[2]), "=r"((r)[3]) : "r"(a))

#define MMA16816(c, a, b0, b1) \
    asm volatile("mma.sync.aligned.m16n8k16.row.col.f32.bf16.bf16.f32 " \
        "{%0,%1,%2,%3},{%4,%5,%6,%7},{%8,%9},{%0,%1,%2,%3};" \
        : "+f"((c)[0]), "+f"((c)[1]), "+f"((c)[2]), "+f"((c)[3]) \
        : "r"((a)[0]), "r"((a)[1]), "r"((a)[2]), "r"((a)[3]), "r"(b0), "r"(b1))

__device__ __forceinline__ void split1(float x, bf16& h, bf16& l) {
    h = __float2bfloat16_rn(x);
    l = __float2bfloat16_rn(x - __bfloat162float(h));
}
__device__ __forceinline__ uint32_t packsplit(float x, float y, uint32_t& lo) {
    __nv_bfloat162 h2 = __floats2bfloat162_rn(x, y);
    float2 hf = __bfloat1622float2(h2);
    __nv_bfloat162 l2 = __floats2bfloat162_rn(x - hf.x, y - hf.y);
    lo = *reinterpret_cast<uint32_t*>(&l2);
    return *reinterpret_cast<uint32_t*>(&h2);
}

// ============ weight transpose + bf16 split: W[K,N] -> Th/Tl[N,K] =============
__global__ __launch_bounds__(256)
void wsplit_t(const float* __restrict__ W, bf16* __restrict__ Th,
              bf16* __restrict__ Tl, int K, int N)
{
    __shared__ float t[32][33];
    const int n0 = blockIdx.x * 32, k0 = blockIdx.y * 32;
    const int tx = threadIdx.x, ty = threadIdx.y;   // 32 x 8
#pragma unroll
    for (int i = 0; i < 4; i++)
        t[ty + i*8][tx] = W[(size_t)(k0 + ty + i*8) * N + n0 + tx];
    __syncthreads();
#pragma unroll
    for (int i = 0; i < 4; i++) {
        const int r = ty + i*8;
        const float v = t[tx][r];
        bf16 h, l; split1(v, h, l);
        Th[(size_t)(n0 + r) * K + k0 + tx] = h;
        Tl[(size_t)(n0 + r) * K + k0 + tx] = l;
    }
}

// ============ activation split: X fp32 [n] -> Xh, Xl bf16 =====================
__global__ __launch_bounds__(256)
void split_act(const float* __restrict__ X, bf16* __restrict__ Xh,
               bf16* __restrict__ Xl, int n4)
{
    const int i = blockIdx.x * 256 + threadIdx.x;
    if (i >= n4) return;
    const float4 v = ((const float4*)X)[i];
    bf16 h0,l0,h1,l1,h2,l2,h3,l3;
    split1(v.x,h0,l0); split1(v.y,h1,l1); split1(v.z,h2,l2); split1(v.w,h3,l3);
    __nv_bfloat162 ph[2] = {{h0,h1},{h2,h3}};
    __nv_bfloat162 pl[2] = {{l0,l1},{l2,l3}};
    ((uint2*)Xh)[i] = *(uint2*)ph;
    ((uint2*)Xl)[i] = *(uint2*)pl;
}

// ========== mma.sync GEMM: C[M,N] = A @ W + bias ==============================
// OUT=0: fp32 C + bias.  OUT=1: relu(C+bias) -> bf16 hi/lo.  OUT=2: C+bias -> bf16 hi/lo.
#define GEMM_SMEM (4*32768)   // 131072

template<int OUT>
__global__ __launch_bounds__(256)
void gemm_ts(const bf16* __restrict__ Ah, const bf16* __restrict__ Al,
             const bf16* __restrict__ Bh, const bf16* __restrict__ Bl,
             const float* __restrict__ bias, float* __restrict__ C,
             bf16* __restrict__ Ch, bf16* __restrict__ Cl, int N, int K)
{
    extern __shared__ char smraw[];
    const uint32_t sb0 = smem_u32(smraw);          // 4 stages x 32768 B
    const int tid  = threadIdx.x;
    const int lane = tid & 31;
    const int w    = tid >> 5;
    const int m0   = blockIdx.y * 128;
    const int n0   = blockIdx.x * 128;
    const int wm   = (w >> 2) * 64;
    const int wn   = (w & 3) * 32;
    const int r15  = lane & 15;
    const int kh   = lane >> 4;

    uint32_t aoff[4][2], boff[2][2];
#pragma unroll
    for (int bm = 0; bm < 4; bm++) {
        const int row = wm + bm*16 + r15;
        const int sw  = (row >> 1) & 3;
#pragma unroll
        for (int ks = 0; ks < 2; ks++)
            aoff[bm][ks] = row*64 + (((ks*2 + kh) ^ sw) << 4);
    }
#pragma unroll
    for (int bp = 0; bp < 2; bp++) {
        const int row = wn + bp*16 + r15;
        const int sw  = (row >> 1) & 3;
#pragma unroll
        for (int ks = 0; ks < 2; ks++)
            boff[bp][ks] = row*64 + (((ks*2 + kh) ^ sw) << 4);
    }

    const bf16* gbase[4] = {Ah + (size_t)m0*K, Al + (size_t)m0*K,
                            Bh + (size_t)n0*K, Bl + (size_t)n0*K};
    auto load_stage = [&](int s, int k0) {
        const uint32_t stb = sb0 + s*32768;
#pragma unroll
        for (int i = 0; i < 8; i++) {
            const int tile = i >> 1;
            const int idx  = ((i & 1) << 8) + tid;
            const int row  = idx >> 2;
            const int c    = idx & 3;
            const int sc   = c ^ ((row >> 1) & 3);
            cpa16(stb + tile*8192 + row*64 + sc*16,
                  gbase[tile] + (size_t)row*K + k0 + c*8);
        }
    };

    float acc[4][4][4];
#pragma unroll
    for (int bm = 0; bm < 4; bm++)
#pragma unroll
        for (int bn = 0; bn < 4; bn++)
#pragma unroll
            for (int j = 0; j < 4; j++) acc[bm][bn][j] = 0.f;

    const int CH = K >> 5;
    load_stage(0, 0);  CPA_COMMIT();
    load_stage(1, 32); CPA_COMMIT();
    load_stage(2, 64); CPA_COMMIT();

    for (int c = 0; c < CH; ++c) {
        CPA_WAIT2();
        __syncthreads();
        if (c + 3 < CH) load_stage((c + 3) & 3, (c + 3) * 32);
        CPA_COMMIT();

        const uint32_t stb = sb0 + (c & 3)*32768;
#pragma unroll
        for (int ks = 0; ks < 2; ks++) {
            uint32_t ah[4][4], al[4][4], bh[2][4], bl[2][4];
#pragma unroll
            for (int bm = 0; bm < 4; bm++) {
                LDSM4(ah[bm], stb +        aoff[bm][ks]);
                LDSM4(al[bm], stb + 8192 + aoff[bm][ks]);
            }
#pragma unroll
            for (int bp = 0; bp < 2; bp++) {
                LDSM4(bh[bp], stb + 16384 + boff[bp][ks]);
                LDSM4(bl[bp], stb + 24576 + boff[bp][ks]);
            }
#pragma unroll
            for (int bm = 0; bm < 4; bm++)
#pragma unroll
                for (int bn = 0; bn < 4; bn++) {
                    const int bp = bn >> 1, sel = bn & 1;
                    MMA16816(acc[bm][bn], ah[bm], bh[bp][sel], bh[bp][sel+2]);
                    MMA16816(acc[bm][bn], ah[bm], bl[bp][sel], bl[bp][sel+2]);
                    MMA16816(acc[bm][bn], al[bm], bh[bp][sel], bh[bp][sel+2]);
                }
        }
    }

    const int er = lane >> 2;
    const int ec = (lane & 3) * 2;
#pragma unroll
    for (int bm = 0; bm < 4; bm++)
#pragma unroll
        for (int bn = 0; bn < 4; bn++) {
            const int col = n0 + wn + bn*8 + ec;
            const float b0 = bias[col], b1 = bias[col+1];
#pragma unroll
            for (int half = 0; half < 2; half++) {
                const int r = m0 + wm + bm*16 + er + half*8;
                float v0 = acc[bm][bn][half*2+0] + b0;
                float v1 = acc[bm][bn][half*2+1] + b1;
                if (OUT == 0) {
                    float2 o = {v0, v1};
                    *(float2*)&C[(size_t)r*N + col] = o;
                } else {
                    if (OUT == 1) { v0 = fmaxf(v0, 0.f); v1 = fmaxf(v1, 0.f); }
                    uint32_t lo;
                    uint32_t hi = packsplit(v0, v1, lo);
                    *(uint32_t*)&Ch[(size_t)r*N + col] = hi;
                    *(uint32_t*)&Cl[(size_t)r*N + col] = lo;
                }
            }
        }
}

// ---------------- fused residual add + LayerNorm (row = 1024) ----------------
template<bool SPLIT>
__global__ __launch_bounds__(256)
void add_ln_kernel(const float* __restrict__ z, const float* __restrict__ res,
                   const float* __restrict__ g, const float* __restrict__ be,
                   float* __restrict__ out, bf16* __restrict__ oh, bf16* __restrict__ ol)
{
    const int row = blockIdx.x;
    const int tid = threadIdx.x;
    const float* zr = z   + (size_t)row*DM;
    const float* rr = res + (size_t)row*DM;

    float v[4];
    float s = 0.f, sq = 0.f;
#pragma unroll
    for (int i = 0; i < 4; i++) {
        const int c = tid + i*256;
        const float x = zr[c] + rr[c];
        v[i] = x; s += x; sq += x*x;
    }
#pragma unroll
    for (int o = 16; o; o >>= 1) {
        s  += __shfl_xor_sync(0xffffffffu, s,  o);
        sq += __shfl_xor_sync(0xffffffffu, sq, o);
    }
    __shared__ float ss[8], ssq[8];
    if ((tid & 31) == 0) { ss[tid >> 5] = s; ssq[tid >> 5] = sq; }
    __syncthreads();
    if (tid < 32) {
        s  = (tid < 8) ? ss[tid]  : 0.f;
        sq = (tid < 8) ? ssq[tid] : 0.f;
#pragma unroll
        for (int o = 4; o; o >>= 1) {
            s  += __shfl_xor_sync(0xffffffffu, s,  o);
            sq += __shfl_xor_sync(0xffffffffu, sq, o);
        }
        if (tid == 0) { ss[0] = s; ssq[0] = sq; }
    }
    __syncthreads();
    const float mean = ss[0] * (1.f/DM);
    const float var  = ssq[0] * (1.f/DM) - mean*mean;
    const float inv  = rsqrtf(var + 1e-5f);
#pragma unroll
    for (int i = 0; i < 4; i++) {
        const int c = tid + i*256;
        const float y = (v[i] - mean)*inv*g[c] + be[c];
        out[(size_t)row*DM + c] = y;
        if (SPLIT) {
            bf16 h, l; split1(y, h, l);
            oh[(size_t)row*DM + c] = h;
            ol[(size_t)row*DM + c] = l;
        }
    }
}

// ---------------- mma.sync flash attention -----------------------------------
// CTA: 128 q-rows, 8 warps (warp = 16 q x 64 k). K-tile 64, double-buffered KV.
// Smem: Qh/Ql (2x16KB) + 2 stages x (Kh,Kl,Vh,Vl = 32KB) = 96KB.
// S = QhKh + QhKl + QlKh (fp32 acc); P packed from S-acc (C-frag == A-frag);
// O += PhVh + PlVh + PhVl.  Output: bf16 hi/lo.
#define ATT_SMEM (32768 + 2*32768)

__global__ __launch_bounds__(256, 2)
void attn_mma(const bf16* __restrict__ Qhg, const bf16* __restrict__ Qlg,
              const bf16* __restrict__ Khg, const bf16* __restrict__ Klg,
              const bf16* __restrict__ Vhg, const bf16* __restrict__ Vlg,
              bf16* __restrict__ Oh, bf16* __restrict__ Ol, int causal)
{
    extern __shared__ char smraw[];
    const uint32_t Qs = smem_u32(smraw);
    const uint32_t St = Qs + 32768;

    const int qi = blockIdx.x, h = blockIdx.y, b = blockIdx.z;
    const int tid = threadIdx.x, lane = tid & 31, w = tid >> 5;
    const int q0 = qi * 128;
    const int wq = w * 16;
    const int rA = lane & 15, gh = lane >> 4;
    const int r4 = lane >> 2, c2 = (lane & 3) * 2;

    // load Q tile (128 rows x 64 d, hi+lo), XOR-granule swizzle
    {
        const bf16* qsrc[2] = {Qhg, Qlg};
#pragma unroll
        for (int it = 0; it < 8; it++) {
            const int idx = tid + it*256;
            const int tile = idx >> 10, row = (idx >> 3) & 127, g = idx & 7;
            cpa16(Qs + tile*16384 + row*128 + ((g ^ (row & 7)) << 4),
                  qsrc[tile] + (size_t)(b*SEQ + q0 + row)*DM + h*HD + g*8);
        }
    }
    CPA_COMMIT();

    const bf16* ksrc[4] = {Khg, Klg, Vhg, Vlg};
    auto load_kv = [&](int s, int k0) {
#pragma unroll
        for (int it = 0; it < 8; it++) {
            const int idx = tid + it*256;
            const int tile = idx >> 9, row = (idx >> 3) & 63, g = idx & 7;
            cpa16(St + s*32768 + tile*8192 + row*128 + ((g ^ (row & 7)) << 4),
                  ksrc[tile] + (size_t)(b*SEQ + k0 + row)*DM + h*HD + g*8);
        }
    };

    const int nt = causal ? (qi*2 + 2) : (SEQ/64);
    load_kv(0, 0);  CPA_COMMIT();
    if (nt > 1) load_kv(1, 64);
    CPA_COMMIT();

    float oacc[8][4];
#pragma unroll
    for (int n = 0; n < 8; n++)
#pragma unroll
        for (int j = 0; j < 4; j++) oacc[n][j] = 0.f;
    float m0 = -1e30f, m1 = -1e30f, l0 = 0.f, l1 = 0.f;

    const int qrow = wq + rA;
    const uint32_t qx  = (uint32_t)qrow * 128;
    const int      qxr = qrow & 7;
    const uint32_t kx  = (uint32_t)rA * 128;
    const int      kxr = rA & 7;

    for (int kt = 0; kt < nt; kt++) {
        CPA_WAIT1();
        __syncthreads();
        const uint32_t stb = St + (kt & 1)*32768;
        const int k0 = kt * 64;

        // ---- S = Q K^T (bf16x3) ----
        float sacc[8][4];
#pragma unroll
        for (int n = 0; n < 8; n++)
#pragma unroll
            for (int j = 0; j < 4; j++) sacc[n][j] = 0.f;
#pragma unroll
        for (int ks = 0; ks < 4; ks++) {
            uint32_t qh_[4], ql_[4];
            const uint32_t qo = qx + (((ks*2 + gh) ^ qxr) << 4);
            LDSM4(qh_, Qs + qo);
            LDSM4(ql_, Qs + 16384 + qo);
#pragma unroll
            for (int bp = 0; bp < 4; bp++) {
                uint32_t kh_[4], kl_[4];
                const uint32_t ko = stb + bp*2048 + kx + (((ks*2 + gh) ^ kxr) << 4);
                LDSM4(kh_, ko);
                LDSM4(kl_, ko + 8192);
#pragma unroll
                for (int sel = 0; sel < 2; sel++) {
                    const int n = bp*2 + sel;
                    MMA16816(sacc[n], qh_, kh_[sel], kh_[sel+2]);
                    MMA16816(sacc[n], qh_, kl_[sel], kl_[sel+2]);
                    MMA16816(sacc[n], ql_, kh_[sel], kh_[sel+2]);
                }
            }
        }

        // ---- scale + causal mask ----
        const int growA = q0 + wq + r4;   // rows: growA (c0,c1), growA+8 (c2,c3)
#pragma unroll
        for (int n = 0; n < 8; n++)
#pragma unroll
            for (int j = 0; j < 4; j++) sacc[n][j] *= 0.125f;
        if (causal && (k0 + 63 > q0)) {
#pragma unroll
            for (int n = 0; n < 8; n++) {
                const int col = k0 + n*8 + c2;
                if (col     > growA)     sacc[n][0] = -1e9f;
                if (col + 1 > growA)     sacc[n][1] = -1e9f;
                if (col     > growA + 8) sacc[n][2] = -1e9f;
                if (col + 1 > growA + 8) sacc[n][3] = -1e9f;
            }
        }

        // ---- online softmax (rows split across 4 lanes) ----
        float tm0 = -1e30f, tm1 = -1e30f;
#pragma unroll
        for (int n = 0; n < 8; n++) {
            tm0 = fmaxf(tm0, fmaxf(sacc[n][0], sacc[n][1]));
            tm1 = fmaxf(tm1, fmaxf(sacc[n][2], sacc[n][3]));
        }
        tm0 = fmaxf(tm0, __shfl_xor_sync(0xffffffffu, tm0, 1));
        tm0 = fmaxf(tm0, __shfl_xor_sync(0xffffffffu, tm0, 2));
        tm1 = fmaxf(tm1, __shfl_xor_sync(0xffffffffu, tm1, 1));
        tm1 = fmaxf(tm1, __shfl_xor_sync(0xffffffffu, tm1, 2));
        const float mn0 = fmaxf(m0, tm0), mn1 = fmaxf(m1, tm1);
        const float a0 = __expf(m0 - mn0), a1 = __expf(m1 - mn1);
        float ps0 = 0.f, ps1 = 0.f;
#pragma unroll
        for (int n = 0; n < 8; n++) {
            sacc[n][0] = __expf(sacc[n][0] - mn0);
            sacc[n][1] = __expf(sacc[n][1] - mn0);
            sacc[n][2] = __expf(sacc[n][2] - mn1);
            sacc[n][3] = __expf(sacc[n][3] - mn1);
            ps0 += sacc[n][0] + sacc[n][1];
            ps1 += sacc[n][2] + sacc[n][3];
        }
        ps0 += __shfl_xor_sync(0xffffffffu, ps0, 1);
        ps0 += __shfl_xor_sync(0xffffffffu, ps0, 2);
        ps1 += __shfl_xor_sync(0xffffffffu, ps1, 1);
        ps1 += __shfl_xor_sync(0xffffffffu, ps1, 2);
        l0 = l0*a0 + ps0;  l1 = l1*a1 + ps1;
        m0 = mn0;          m1 = mn1;
#pragma unroll
        for (int n = 0; n < 8; n++) {
            oacc[n][0] *= a0; oacc[n][1] *= a0;
            oacc[n][2] *= a1; oacc[n][3] *= a1;
        }

        // ---- pack P into A-fragments (hi/lo) ----
        uint32_t pha[4][4], pla[4][4];
#pragma unroll
        for (int ks = 0; ks < 4; ks++) {
            const int n0b = 2*ks, n1b = n0b + 1;
            pha[ks][0] = packsplit(sacc[n0b][0], sacc[n0b][1], pla[ks][0]);
            pha[ks][1] = packsplit(sacc[n0b][2], sacc[n0b][3], pla[ks][1]);
            pha[ks][2] = packsplit(sacc[n1b][0], sacc[n1b][1], pla[ks][2]);
            pha[ks][3] = packsplit(sacc[n1b][2], sacc[n1b][3], pla[ks][3]);
        }

        // ---- O += P V (3-term split), V via ldmatrix.trans ----
#pragma unroll
        for (int ks = 0; ks < 4; ks++) {
#pragma unroll
            for (int gp = 0; gp < 4; gp++) {
                uint32_t vh_[4], vl_[4];
                const uint32_t vo = stb + 16384 + (uint32_t)(ks*16 + rA)*128
                                  + (((gp*2 + gh) ^ kxr) << 4);
                LDSM4T(vh_, vo);
                LDSM4T(vl_, vo + 8192);
                const int n = gp*2;
                MMA16816(oacc[n],   pha[ks], vh_[0], vh_[1]);
                MMA16816(oacc[n+1], pha[ks], vh_[2], vh_[3]);
                MMA16816(oacc[n],   pla[ks], vh_[0], vh_[1]);
                MMA16816(oacc[n+1], pla[ks], vh_[2], vh_[3]);
                MMA16816(oacc[n],   pha[ks], vl_[0], vl_[1]);
                MMA16816(oacc[n+1], pha[ks], vl_[2], vl_[3]);
            }
        }
        __syncthreads();
        if (kt + 2 < nt) load_kv(kt & 1, (kt + 2)*64);
        CPA_COMMIT();
    }

    // ---- epilogue: O / l, split to bf16 hi/lo ----
    const float il0 = 1.f / l0, il1 = 1.f / l1;
    const size_t row0 = (size_t)(b*SEQ + q0 + wq + r4)*DM + h*HD;
    const size_t row1 = row0 + (size_t)8*DM;
#pragma unroll
    for (int n = 0; n < 8; n++) {
        const int col = n*8 + c2;
        uint32_t lo0, lo1;
        const uint32_t hi0 = packsplit(oacc[n][0]*il0, oacc[n][1]*il0, lo0);
        const uint32_t hi1 = packsplit(oacc[n][2]*il1, oacc[n][3]*il1, lo1);
        *(uint32_t*)&Oh[row0 + col] = hi0;
        *(uint32_t*)&Ol[row0 + col] = lo0;
        *(uint32_t*)&Oh[row1 + col] = hi1;
        *(uint32_t*)&Ol[row1 + col] = lo1;
    }
}

// ---------------- launch ------------------------------------------------------
extern "C" void kernel_launch(void* const* d_in, const int* in_sizes, int n_in,
                              void* d_out, int out_size)
{
    (void)in_sizes; (void)n_in; (void)out_size;
    const float* dec = (const float*)d_in[0];
    const float* enc = (const float*)d_in[1];
    const float* bq1 = (const float*)d_in[5];
    const float* bk1 = (const float*)d_in[7];
    const float* bv1 = (const float*)d_in[9];
    const float* zb1 = (const float*)d_in[11];
    const float* g1  = (const float*)d_in[12];
    const float* be1 = (const float*)d_in[13];
    const float* bq2 = (const float*)d_in[15];
    const float* bk2 = (const float*)d_in[17];
    const float* bv2 = (const float*)d_in[19];
    const float* zb2 = (const float*)d_in[21];
    const float* g2  = (const float*)d_in[22];
    const float* be2 = (const float*)d_in[23];
    const float* fb1 = (const float*)d_in[25];
    const float* fb2 = (const float*)d_in[27];
    const float* g3  = (const float*)d_in[28];
    const float* be3 = (const float*)d_in[29];
    float* out = (float*)d_out;

    float *zp, *o1p, *o2p;
    bf16 *dech,*decl,*ench,*encl,*qh,*ql,*kh,*kl,*vh,*vl;
    bf16 *aoh,*aol,*o1h,*o1l,*o2h,*o2l,*ffh,*ffl,*whp,*wlp;
    cudaGetSymbolAddress((void**)&zp,  g_z);
    cudaGetSymbolAddress((void**)&o1p, g_o1);
    cudaGetSymbolAddress((void**)&o2p, g_o2);
    cudaGetSymbolAddress((void**)&dech, g_dech); cudaGetSymbolAddress((void**)&decl, g_decl);
    cudaGetSymbolAddress((void**)&ench, g_ench); cudaGetSymbolAddress((void**)&encl, g_encl);
    cudaGetSymbolAddress((void**)&qh, g_qh); cudaGetSymbolAddress((void**)&ql, g_ql);
    cudaGetSymbolAddress((void**)&kh, g_kh); cudaGetSymbolAddress((void**)&kl, g_kl);
    cudaGetSymbolAddress((void**)&vh, g_vh); cudaGetSymbolAddress((void**)&vl, g_vl);
    cudaGetSymbolAddress((void**)&aoh,  g_aoh);  cudaGetSymbolAddress((void**)&aol,  g_aol);
    cudaGetSymbolAddress((void**)&o1h,  g_o1h);  cudaGetSymbolAddress((void**)&o1l,  g_o1l);
    cudaGetSymbolAddress((void**)&o2h,  g_o2h);  cudaGetSymbolAddress((void**)&o2l,  g_o2l);
    cudaGetSymbolAddress((void**)&ffh,  g_ffh);  cudaGetSymbolAddress((void**)&ffl,  g_ffl);
    cudaGetSymbolAddress((void**)&whp,  g_wh);   cudaGetSymbolAddress((void**)&wlp,  g_wl);

    cudaFuncSetAttribute(attn_mma,   cudaFuncAttributeMaxDynamicSharedMemorySize, ATT_SMEM);
    cudaFuncSetAttribute(gemm_ts<0>, cudaFuncAttributeMaxDynamicSharedMemorySize, GEMM_SMEM);
    cudaFuncSetAttribute(gemm_ts<1>, cudaFuncAttributeMaxDynamicSharedMemorySize, GEMM_SMEM);
    cudaFuncSetAttribute(gemm_ts<2>, cudaFuncAttributeMaxDynamicSharedMemorySize, GEMM_SMEM);

    // ---- weight transpose + split ----
    {
        const dim3 b(32, 8);
        wsplit_t<<<dim3(32, 32),  b>>>((const float*)d_in[4],  whp + 0*MEG,  wlp + 0*MEG,  DM,  DM);
        wsplit_t<<<dim3(32, 32),  b>>>((const float*)d_in[6],  whp + 1*MEG,  wlp + 1*MEG,  DM,  DM);
        wsplit_t<<<dim3(32, 32),  b>>>((const float*)d_in[8],  whp + 2*MEG,  wlp + 2*MEG,  DM,  DM);
        wsplit_t<<<dim3(32, 32),  b>>>((const float*)d_in[10], whp + 3*MEG,  wlp + 3*MEG,  DM,  DM);
        wsplit_t<<<dim3(32, 32),  b>>>((const float*)d_in[14], whp + 4*MEG,  wlp + 4*MEG,  DM,  DM);
        wsplit_t<<<dim3(32, 32),  b>>>((const float*)d_in[16], whp + 5*MEG,  wlp + 5*MEG,  DM,  DM);
        wsplit_t<<<dim3(32, 32),  b>>>((const float*)d_in[18], whp + 6*MEG,  wlp + 6*MEG,  DM,  DM);
        wsplit_t<<<dim3(32, 32),  b>>>((const float*)d_in[20], whp + 7*MEG,  wlp + 7*MEG,  DM,  DM);
        wsplit_t<<<dim3(128, 32), b>>>((const float*)d_in[24], whp + 8*MEG,  wlp + 8*MEG,  DM,  FFD);
        wsplit_t<<<dim3(32, 128), b>>>((const float*)d_in[26], whp + 12*MEG, wlp + 12*MEG, FFD, DM);
    }
    // ---- input splits ----
    split_act<<<TOK*DM/1024, 256>>>(dec, dech, decl, TOK*DM/4);
    split_act<<<TOK*DM/1024, 256>>>(enc, ench, encl, TOK*DM/4);

    const dim3 gD (8, 32);     // N=1024
    const dim3 gFF(32, 32);    // N=4096
    const dim3 gA (SEQ/128, NH, BB);

    // ---- self-attention block ----
    gemm_ts<2><<<gD, 256, GEMM_SMEM>>>(dech, decl, whp + 0*MEG, wlp + 0*MEG, bq1, 0, qh, ql, DM, DM);
    gemm_ts<2><<<gD, 256, GEMM_SMEM>>>(dech, decl, whp + 1*MEG, wlp + 1*MEG, bk1, 0, kh, kl, DM, DM);
    gemm_ts<2><<<gD, 256, GEMM_SMEM>>>(dech, decl, whp + 2*MEG, wlp + 2*MEG, bv1, 0, vh, vl, DM, DM);
    attn_mma<<<gA, 256, ATT_SMEM>>>(qh, ql, kh, kl, vh, vl, aoh, aol, 1);
    gemm_ts<0><<<gD, 256, GEMM_SMEM>>>(aoh, aol, whp + 3*MEG, wlp + 3*MEG, zb1, zp, 0, 0, DM, DM);
    add_ln_kernel<true><<<TOK, 256>>>(zp, dec, g1, be1, o1p, o1h, o1l);

    // ---- cross-attention block ----
    gemm_ts<2><<<gD, 256, GEMM_SMEM>>>(o1h, o1l, whp + 4*MEG, wlp + 4*MEG, bq2, 0, qh, ql, DM, DM);
    gemm_ts<2><<<gD, 256, GEMM_SMEM>>>(ench, encl, whp + 5*MEG, wlp + 5*MEG, bk2, 0, kh, kl, DM, DM);
    gemm_ts<2><<<gD, 256, GEMM_SMEM>>>(ench, encl, whp + 6*MEG, wlp + 6*MEG, bv2, 0, vh, vl, DM, DM);
    attn_mma<<<gA, 256, ATT_SMEM>>>(qh, ql, kh, kl, vh, vl, aoh, aol, 0);
    gemm_ts<0><<<gD, 256, GEMM_SMEM>>>(aoh, aol, whp + 7*MEG, wlp + 7*MEG, zb2, zp, 0, 0, DM, DM);
    add_ln_kernel<true><<<TOK, 256>>>(zp, o1p, g2, be2, o2p, o2h, o2l);

    // ---- feed-forward block ----
    gemm_ts<1><<<gFF, 256, GEMM_SMEM>>>(o2h, o2l, whp + 8*MEG,  wlp + 8*MEG,  fb1, 0, ffh, ffl, FFD, DM);
    gemm_ts<0><<<gD,  256, GEMM_SMEM>>>(ffh, ffl, whp + 12*MEG, wlp + 12*MEG, fb2, zp, 0, 0, DM, FFD);
    add_ln_kernel<false><<<TOK, 256>>>(zp, o2p, g3, be3, out, 0, 0);
}

// round 8
// speedup vs baseline: 2.1975x; 1.0204x over previous
#include <cuda_runtime.h>
#include <cuda_bf16.h>
#include <math.h>
#include <stdint.h>

// Problem constants
#define BB   4
#define SEQ  1024
#define DM   1024
#define NH   16
#define HD   64
#define FFD  4096
#define TOK  (BB*SEQ)   // 4096
#define MEG  (1024*1024)

typedef __nv_bfloat16 bf16;

// ---------------- scratch (device globals: no allocs allowed) ----------------
__device__ float g_z  [TOK*DM];
__device__ float g_o1 [TOK*DM];
__device__ float g_o2 [TOK*DM];
__device__ bf16  g_dech[TOK*DM], g_decl[TOK*DM];
__device__ bf16  g_ench[TOK*DM], g_encl[TOK*DM];
__device__ bf16  g_qh [TOK*DM], g_ql [TOK*DM];
__device__ bf16  g_kh [TOK*DM], g_kl [TOK*DM];
__device__ bf16  g_vh [TOK*DM], g_vl [TOK*DM];
__device__ bf16  g_aoh [TOK*DM], g_aol [TOK*DM];
__device__ bf16  g_o1h [TOK*DM], g_o1l [TOK*DM];
__device__ bf16  g_o2h [TOK*DM], g_o2l [TOK*DM];
__device__ bf16  g_ffh [TOK*FFD], g_ffl[TOK*FFD];
__device__ bf16  g_wh[16*MEG], g_wl[16*MEG];

// ==================== low-level helpers (sm_100 baseline ISA) =================
__device__ __forceinline__ uint32_t smem_u32(const void* p) {
    uint32_t a;
    asm("{ .reg .u64 t; cvta.to.shared.u64 t, %1; cvt.u32.u64 %0, t; }" : "=r"(a) : "l"(p));
    return a;
}
__device__ __forceinline__ void cpa16(uint32_t s, const void* g) {
    asm volatile("cp.async.cg.shared.global [%0], [%1], 16;" :: "r"(s), "l"(g));
}
#define CPA_COMMIT() asm volatile("cp.async.commit_group;" ::: "memory")
#define CPA_WAIT1()  asm volatile("cp.async.wait_group 1;"  ::: "memory")
#define CPA_WAIT2()  asm volatile("cp.async.wait_group 2;"  ::: "memory")

#define LDSM4(r, a) \
    asm volatile("ldmatrix.sync.aligned.m8n8.x4.shared.b16 {%0,%1,%2,%3}, [%4];" \
        : "=r"((r)[0]), "=r"((r)[1]), "=r"((r)[2]), "=r"((r)[3]) : "r"(a))
#define LDSM4T(r, a) \
    asm volatile("ldmatrix.sync.aligned.m8n8.x4.trans.shared.b16 {%0,%1,%2,%3}, [%4];" \
        : "=r"((r)[0]), "=r"((r)[1]), "=r"((r)[2]), "=r"((r)[3]) : "r"(a))

#define MMA16816(c, a, b0, b1) \
    asm volatile("mma.sync.aligned.m16n8k16.row.col.f32.bf16.bf16.f32 " \
        "{%0,%1,%2,%3},{%4,%5,%6,%7},{%8,%9},{%0,%1,%2,%3};" \
        : "+f"((c)[0]), "+f"((c)[1]), "+f"((c)[2]), "+f"((c)[3]) \
        : "r"((a)[0]), "r"((a)[1]), "r"((a)[2]), "r"((a)[3]), "r"(b0), "r"(b1))

__device__ __forceinline__ void split1(float x, bf16& h, bf16& l) {
    h = __float2bfloat16_rn(x);
    l = __float2bfloat16_rn(x - __bfloat162float(h));
}
__device__ __forceinline__ uint32_t packsplit(float x, float y, uint32_t& lo) {
    __nv_bfloat162 h2 = __floats2bfloat162_rn(x, y);
    float2 hf = __bfloat1622float2(h2);
    __nv_bfloat162 l2 = __floats2bfloat162_rn(x - hf.x, y - hf.y);
    lo = *reinterpret_cast<uint32_t*>(&l2);
    return *reinterpret_cast<uint32_t*>(&h2);
}

// ============ weight transpose + bf16 split: W[K,N] -> Th/Tl[N,K] =============
__global__ __launch_bounds__(256)
void wsplit_t(const float* __restrict__ W, bf16* __restrict__ Th,
              bf16* __restrict__ Tl, int K, int N)
{
    __shared__ float t[32][33];
    const int n0 = blockIdx.x * 32, k0 = blockIdx.y * 32;
    const int tx = threadIdx.x, ty = threadIdx.y;   // 32 x 8
#pragma unroll
    for (int i = 0; i < 4; i++)
        t[ty + i*8][tx] = W[(size_t)(k0 + ty + i*8) * N + n0 + tx];
    __syncthreads();
#pragma unroll
    for (int i = 0; i < 4; i++) {
        const int r = ty + i*8;
        const float v = t[tx][r];
        bf16 h, l; split1(v, h, l);
        Th[(size_t)(n0 + r) * K + k0 + tx] = h;
        Tl[(size_t)(n0 + r) * K + k0 + tx] = l;
    }
}

// ============ activation split: X fp32 [n] -> Xh, Xl bf16 =====================
__global__ __launch_bounds__(256)
void split_act(const float* __restrict__ X, bf16* __restrict__ Xh,
               bf16* __restrict__ Xl, int n4)
{
    const int i = blockIdx.x * 256 + threadIdx.x;
    if (i >= n4) return;
    const float4 v = ((const float4*)X)[i];
    bf16 h0,l0,h1,l1,h2,l2,h3,l3;
    split1(v.x,h0,l0); split1(v.y,h1,l1); split1(v.z,h2,l2); split1(v.w,h3,l3);
    __nv_bfloat162 ph[2] = {{h0,h1},{h2,h3}};
    __nv_bfloat162 pl[2] = {{l0,l1},{l2,l3}};
    ((uint2*)Xh)[i] = *(uint2*)ph;
    ((uint2*)Xl)[i] = *(uint2*)pl;
}

// ========== mma.sync GEMM: C[M,N] = A @ W + bias ==============================
// CTA 256x128, 8 warps (warp tile 64x64), BK=32, 4-stage cp.async pipeline.
// OUT=0: fp32 C + bias.  OUT=1: relu(C+bias) -> bf16 hi/lo.  OUT=2: C+bias -> bf16 hi/lo.
#define GEMM_SMEM (4*49152)   // 196608

template<int OUT>
__global__ __launch_bounds__(256)
void gemm_ts(const bf16* __restrict__ Ah, const bf16* __restrict__ Al,
             const bf16* __restrict__ Bh, const bf16* __restrict__ Bl,
             const float* __restrict__ bias, float* __restrict__ C,
             bf16* __restrict__ Ch, bf16* __restrict__ Cl, int N, int K)
{
    extern __shared__ char smraw[];
    const uint32_t sb0 = smem_u32(smraw);          // 4 stages x 49152 B
    const int tid  = threadIdx.x;
    const int lane = tid & 31;
    const int w    = tid >> 5;
    const int m0   = blockIdx.y * 256;
    const int n0   = blockIdx.x * 128;
    const int wm   = (w >> 1) * 64;     // 4 warp-rows
    const int wn   = (w & 1) * 64;      // 2 warp-cols
    const int r15  = lane & 15;
    const int kh   = lane >> 4;

    // swizzled ldmatrix byte offsets within a tile (64B rows, 16B granules)
    uint32_t aoff[4][2], boff[4][2];
#pragma unroll
    for (int bm = 0; bm < 4; bm++) {
        const int row = wm + bm*16 + r15;          // 0..255 in A tile
        const int sw  = (row >> 1) & 3;
#pragma unroll
        for (int ks = 0; ks < 2; ks++)
            aoff[bm][ks] = row*64 + (((ks*2 + kh) ^ sw) << 4);
    }
#pragma unroll
    for (int bp = 0; bp < 4; bp++) {
        const int row = wn + bp*16 + r15;          // 0..127 in B tile
        const int sw  = (row >> 1) & 3;
#pragma unroll
        for (int ks = 0; ks < 2; ks++)
            boff[bp][ks] = row*64 + (((ks*2 + kh) ^ sw) << 4);
    }

    // stage layout: Ah@0 (16KB), Al@16K, Bh@32K (8KB), Bl@40K; stride 48KB
    const bf16* gA[2] = {Ah + (size_t)m0*K, Al + (size_t)m0*K};
    const bf16* gB[2] = {Bh + (size_t)n0*K, Bl + (size_t)n0*K};
    auto load_stage = [&](int s, int k0) {
        const uint32_t stb = sb0 + s*49152;
#pragma unroll
        for (int t = 0; t < 2; t++) {
#pragma unroll
            for (int i = 0; i < 4; i++) {            // A: 1024 x 16B chunks
                const int idx = i*256 + tid;
                const int row = idx >> 2;
                const int cc  = idx & 3;
                const int sc  = cc ^ ((row >> 1) & 3);
                cpa16(stb + t*16384 + row*64 + sc*16,
                      gA[t] + (size_t)row*K + k0 + cc*8);
            }
        }
#pragma unroll
        for (int t = 0; t < 2; t++) {
#pragma unroll
            for (int i = 0; i < 2; i++) {            // B: 512 x 16B chunks
                const int idx = i*256 + tid;
                const int row = idx >> 2;
                const int cc  = idx & 3;
                const int sc  = cc ^ ((row >> 1) & 3);
                cpa16(stb + 32768 + t*8192 + row*64 + sc*16,
                      gB[t] + (size_t)row*K + k0 + cc*8);
            }
        }
    };

    float acc[4][8][4];
#pragma unroll
    for (int bm = 0; bm < 4; bm++)
#pragma unroll
        for (int bn = 0; bn < 8; bn++)
#pragma unroll
            for (int j = 0; j < 4; j++) acc[bm][bn][j] = 0.f;

    const int CH = K >> 5;
    load_stage(0, 0);  CPA_COMMIT();
    load_stage(1, 32); CPA_COMMIT();
    load_stage(2, 64); CPA_COMMIT();

    for (int c = 0; c < CH; ++c) {
        CPA_WAIT2();
        __syncthreads();
        if (c + 3 < CH) load_stage((c + 3) & 3, (c + 3) * 32);
        CPA_COMMIT();

        const uint32_t stb = sb0 + (c & 3)*49152;
#pragma unroll
        for (int ks = 0; ks < 2; ks++) {
            uint32_t ah[4][4], al[4][4], bh[4][4], bl[4][4];
#pragma unroll
            for (int bm = 0; bm < 4; bm++) {
                LDSM4(ah[bm], stb +         aoff[bm][ks]);
                LDSM4(al[bm], stb + 16384 + aoff[bm][ks]);
            }
#pragma unroll
            for (int bp = 0; bp < 4; bp++) {
                LDSM4(bh[bp], stb + 32768 + boff[bp][ks]);
                LDSM4(bl[bp], stb + 40960 + boff[bp][ks]);
            }
#pragma unroll
            for (int bm = 0; bm < 4; bm++)
#pragma unroll
                for (int bp = 0; bp < 4; bp++)
#pragma unroll
                    for (int sel = 0; sel < 2; sel++) {
                        const int bn = bp*2 + sel;
                        MMA16816(acc[bm][bn], ah[bm], bh[bp][sel], bh[bp][sel+2]);
                        MMA16816(acc[bm][bn], ah[bm], bl[bp][sel], bl[bp][sel+2]);
                        MMA16816(acc[bm][bn], al[bm], bh[bp][sel], bh[bp][sel+2]);
                    }
        }
    }

    const int er = lane >> 2;
    const int ec = (lane & 3) * 2;
#pragma unroll
    for (int bm = 0; bm < 4; bm++)
#pragma unroll
        for (int bn = 0; bn < 8; bn++) {
            const int col = n0 + wn + bn*8 + ec;
            const float b0 = bias[col], b1 = bias[col+1];
#pragma unroll
            for (int half = 0; half < 2; half++) {
                const int r = m0 + wm + bm*16 + er + half*8;
                float v0 = acc[bm][bn][half*2+0] + b0;
                float v1 = acc[bm][bn][half*2+1] + b1;
                if (OUT == 0) {
                    float2 o = {v0, v1};
                    *(float2*)&C[(size_t)r*N + col] = o;
                } else {
                    if (OUT == 1) { v0 = fmaxf(v0, 0.f); v1 = fmaxf(v1, 0.f); }
                    uint32_t lo;
                    uint32_t hi = packsplit(v0, v1, lo);
                    *(uint32_t*)&Ch[(size_t)r*N + col] = hi;
                    *(uint32_t*)&Cl[(size_t)r*N + col] = lo;
                }
            }
        }
}

// ---------------- fused residual add + LayerNorm (row = 1024) ----------------
template<bool SPLIT>
__global__ __launch_bounds__(256)
void add_ln_kernel(const float* __restrict__ z, const float* __restrict__ res,
                   const float* __restrict__ g, const float* __restrict__ be,
                   float* __restrict__ out, bf16* __restrict__ oh, bf16* __restrict__ ol)
{
    const int row = blockIdx.x;
    const int tid = threadIdx.x;
    const float* zr = z   + (size_t)row*DM;
    const float* rr = res + (size_t)row*DM;

    float v[4];
    float s = 0.f, sq = 0.f;
#pragma unroll
    for (int i = 0; i < 4; i++) {
        const int c = tid + i*256;
        const float x = zr[c] + rr[c];
        v[i] = x; s += x; sq += x*x;
    }
#pragma unroll
    for (int o = 16; o; o >>= 1) {
        s  += __shfl_xor_sync(0xffffffffu, s,  o);
        sq += __shfl_xor_sync(0xffffffffu, sq, o);
    }
    __shared__ float ss[8], ssq[8];
    if ((tid & 31) == 0) { ss[tid >> 5] = s; ssq[tid >> 5] = sq; }
    __syncthreads();
    if (tid < 32) {
        s  = (tid < 8) ? ss[tid]  : 0.f;
        sq = (tid < 8) ? ssq[tid] : 0.f;
#pragma unroll
        for (int o = 4; o; o >>= 1) {
            s  += __shfl_xor_sync(0xffffffffu, s,  o);
            sq += __shfl_xor_sync(0xffffffffu, sq, o);
        }
        if (tid == 0) { ss[0] = s; ssq[0] = sq; }
    }
    __syncthreads();
    const float mean = ss[0] * (1.f/DM);
    const float var  = ssq[0] * (1.f/DM) - mean*mean;
    const float inv  = rsqrtf(var + 1e-5f);
#pragma unroll
    for (int i = 0; i < 4; i++) {
        const int c = tid + i*256;
        const float y = (v[i] - mean)*inv*g[c] + be[c];
        out[(size_t)row*DM + c] = y;
        if (SPLIT) {
            bf16 h, l; split1(y, h, l);
            oh[(size_t)row*DM + c] = h;
            ol[(size_t)row*DM + c] = l;
        }
    }
}

// ---------------- mma.sync flash attention -----------------------------------
#define ATT_SMEM (32768 + 2*32768)

__global__ __launch_bounds__(256, 2)
void attn_mma(const bf16* __restrict__ Qhg, const bf16* __restrict__ Qlg,
              const bf16* __restrict__ Khg, const bf16* __restrict__ Klg,
              const bf16* __restrict__ Vhg, const bf16* __restrict__ Vlg,
              bf16* __restrict__ Oh, bf16* __restrict__ Ol, int causal)
{
    extern __shared__ char smraw[];
    const uint32_t Qs = smem_u32(smraw);
    const uint32_t St = Qs + 32768;

    const int qi = blockIdx.x, h = blockIdx.y, b = blockIdx.z;
    const int tid = threadIdx.x, lane = tid & 31, w = tid >> 5;
    const int q0 = qi * 128;
    const int wq = w * 16;
    const int rA = lane & 15, gh = lane >> 4;
    const int r4 = lane >> 2, c2 = (lane & 3) * 2;

    {
        const bf16* qsrc[2] = {Qhg, Qlg};
#pragma unroll
        for (int it = 0; it < 8; it++) {
            const int idx = tid + it*256;
            const int tile = idx >> 10, row = (idx >> 3) & 127, g = idx & 7;
            cpa16(Qs + tile*16384 + row*128 + ((g ^ (row & 7)) << 4),
                  qsrc[tile] + (size_t)(b*SEQ + q0 + row)*DM + h*HD + g*8);
        }
    }
    CPA_COMMIT();

    const bf16* ksrc[4] = {Khg, Klg, Vhg, Vlg};
    auto load_kv = [&](int s, int k0) {
#pragma unroll
        for (int it = 0; it < 8; it++) {
            const int idx = tid + it*256;
            const int tile = idx >> 9, row = (idx >> 3) & 63, g = idx & 7;
            cpa16(St + s*32768 + tile*8192 + row*128 + ((g ^ (row & 7)) << 4),
                  ksrc[tile] + (size_t)(b*SEQ + k0 + row)*DM + h*HD + g*8);
        }
    };

    const int nt = causal ? (qi*2 + 2) : (SEQ/64);
    load_kv(0, 0);  CPA_COMMIT();
    if (nt > 1) load_kv(1, 64);
    CPA_COMMIT();

    float oacc[8][4];
#pragma unroll
    for (int n = 0; n < 8; n++)
#pragma unroll
        for (int j = 0; j < 4; j++) oacc[n][j] = 0.f;
    float m0 = -1e30f, m1 = -1e30f, l0 = 0.f, l1 = 0.f;

    const int qrow = wq + rA;
    const uint32_t qx  = (uint32_t)qrow * 128;
    const int      qxr = qrow & 7;
    const uint32_t kx  = (uint32_t)rA * 128;
    const int      kxr = rA & 7;

    for (int kt = 0; kt < nt; kt++) {
        CPA_WAIT1();
        __syncthreads();
        const uint32_t stb = St + (kt & 1)*32768;
        const int k0 = kt * 64;

        float sacc[8][4];
#pragma unroll
        for (int n = 0; n < 8; n++)
#pragma unroll
            for (int j = 0; j < 4; j++) sacc[n][j] = 0.f;
#pragma unroll
        for (int ks = 0; ks < 4; ks++) {
            uint32_t qh_[4], ql_[4];
            const uint32_t qo = qx + (((ks*2 + gh) ^ qxr) << 4);
            LDSM4(qh_, Qs + qo);
            LDSM4(ql_, Qs + 16384 + qo);
#pragma unroll
            for (int bp = 0; bp < 4; bp++) {
                uint32_t kh_[4], kl_[4];
                const uint32_t ko = stb + bp*2048 + kx + (((ks*2 + gh) ^ kxr) << 4);
                LDSM4(kh_, ko);
                LDSM4(kl_, ko + 8192);
#pragma unroll
                for (int sel = 0; sel < 2; sel++) {
                    const int n = bp*2 + sel;
                    MMA16816(sacc[n], qh_, kh_[sel], kh_[sel+2]);
                    MMA16816(sacc[n], qh_, kl_[sel], kl_[sel+2]);
                    MMA16816(sacc[n], ql_, kh_[sel], kh_[sel+2]);
                }
            }
        }

        const int growA = q0 + wq + r4;
#pragma unroll
        for (int n = 0; n < 8; n++)
#pragma unroll
            for (int j = 0; j < 4; j++) sacc[n][j] *= 0.125f;
        if (causal && (k0 + 63 > q0)) {
#pragma unroll
            for (int n = 0; n < 8; n++) {
                const int col = k0 + n*8 + c2;
                if (col     > growA)     sacc[n][0] = -1e9f;
                if (col + 1 > growA)     sacc[n][1] = -1e9f;
                if (col     > growA + 8) sacc[n][2] = -1e9f;
                if (col + 1 > growA + 8) sacc[n][3] = -1e9f;
            }
        }

        float tm0 = -1e30f, tm1 = -1e30f;
#pragma unroll
        for (int n = 0; n < 8; n++) {
            tm0 = fmaxf(tm0, fmaxf(sacc[n][0], sacc[n][1]));
            tm1 = fmaxf(tm1, fmaxf(sacc[n][2], sacc[n][3]));
        }
        tm0 = fmaxf(tm0, __shfl_xor_sync(0xffffffffu, tm0, 1));
        tm0 = fmaxf(tm0, __shfl_xor_sync(0xffffffffu, tm0, 2));
        tm1 = fmaxf(tm1, __shfl_xor_sync(0xffffffffu, tm1, 1));
        tm1 = fmaxf(tm1, __shfl_xor_sync(0xffffffffu, tm1, 2));
        const float mn0 = fmaxf(m0, tm0), mn1 = fmaxf(m1, tm1);
        const float a0 = __expf(m0 - mn0), a1 = __expf(m1 - mn1);
        float ps0 = 0.f, ps1 = 0.f;
#pragma unroll
        for (int n = 0; n < 8; n++) {
            sacc[n][0] = __expf(sacc[n][0] - mn0);
            sacc[n][1] = __expf(sacc[n][1] - mn0);
            sacc[n][2] = __expf(sacc[n][2] - mn1);
            sacc[n][3] = __expf(sacc[n][3] - mn1);
            ps0 += sacc[n][0] + sacc[n][1];
            ps1 += sacc[n][2] + sacc[n][3];
        }
        ps0 += __shfl_xor_sync(0xffffffffu, ps0, 1);
        ps0 += __shfl_xor_sync(0xffffffffu, ps0, 2);
        ps1 += __shfl_xor_sync(0xffffffffu, ps1, 1);
        ps1 += __shfl_xor_sync(0xffffffffu, ps1, 2);
        l0 = l0*a0 + ps0;  l1 = l1*a1 + ps1;
        m0 = mn0;          m1 = mn1;
#pragma unroll
        for (int n = 0; n < 8; n++) {
            oacc[n][0] *= a0; oacc[n][1] *= a0;
            oacc[n][2] *= a1; oacc[n][3] *= a1;
        }

        uint32_t pha[4][4], pla[4][4];
#pragma unroll
        for (int ks = 0; ks < 4; ks++) {
            const int n0b = 2*ks, n1b = n0b + 1;
            pha[ks][0] = packsplit(sacc[n0b][0], sacc[n0b][1], pla[ks][0]);
            pha[ks][1] = packsplit(sacc[n0b][2], sacc[n0b][3], pla[ks][1]);
            pha[ks][2] = packsplit(sacc[n1b][0], sacc[n1b][1], pla[ks][2]);
            pha[ks][3] = packsplit(sacc[n1b][2], sacc[n1b][3], pla[ks][3]);
        }

#pragma unroll
        for (int ks = 0; ks < 4; ks++) {
#pragma unroll
            for (int gp = 0; gp < 4; gp++) {
                uint32_t vh_[4], vl_[4];
                const uint32_t vo = stb + 16384 + (uint32_t)(ks*16 + rA)*128
                                  + (((gp*2 + gh) ^ kxr) << 4);
                LDSM4T(vh_, vo);
                LDSM4T(vl_, vo + 8192);
                const int n = gp*2;
                MMA16816(oacc[n],   pha[ks], vh_[0], vh_[1]);
                MMA16816(oacc[n+1], pha[ks], vh_[2], vh_[3]);
                MMA16816(oacc[n],   pla[ks], vh_[0], vh_[1]);
                MMA16816(oacc[n+1], pla[ks], vh_[2], vh_[3]);
                MMA16816(oacc[n],   pha[ks], vl_[0], vl_[1]);
                MMA16816(oacc[n+1], pha[ks], vl_[2], vl_[3]);
            }
        }
        __syncthreads();
        if (kt + 2 < nt) load_kv(kt & 1, (kt + 2)*64);
        CPA_COMMIT();
    }

    const float il0 = 1.f / l0, il1 = 1.f / l1;
    const size_t row0 = (size_t)(b*SEQ + q0 + wq + r4)*DM + h*HD;
    const size_t row1 = row0 + (size_t)8*DM;
#pragma unroll
    for (int n = 0; n < 8; n++) {
        const int col = n*8 + c2;
        uint32_t lo0, lo1;
        const uint32_t hi0 = packsplit(oacc[n][0]*il0, oacc[n][1]*il0, lo0);
        const uint32_t hi1 = packsplit(oacc[n][2]*il1, oacc[n][3]*il1, lo1);
        *(uint32_t*)&Oh[row0 + col] = hi0;
        *(uint32_t*)&Ol[row0 + col] = lo0;
        *(uint32_t*)&Oh[row1 + col] = hi1;
        *(uint32_t*)&Ol[row1 + col] = lo1;
    }
}

// ---------------- launch ------------------------------------------------------
extern "C" void kernel_launch(void* const* d_in, const int* in_sizes, int n_in,
                              void* d_out, int out_size)
{
    (void)in_sizes; (void)n_in; (void)out_size;
    const float* dec = (const float*)d_in[0];
    const float* enc = (const float*)d_in[1];
    const float* bq1 = (const float*)d_in[5];
    const float* bk1 = (const float*)d_in[7];
    const float* bv1 = (const float*)d_in[9];
    const float* zb1 = (const float*)d_in[11];
    const float* g1  = (const float*)d_in[12];
    const float* be1 = (const float*)d_in[13];
    const float* bq2 = (const float*)d_in[15];
    const float* bk2 = (const float*)d_in[17];
    const float* bv2 = (const float*)d_in[19];
    const float* zb2 = (const float*)d_in[21];
    const float* g2  = (const float*)d_in[22];
    const float* be2 = (const float*)d_in[23];
    const float* fb1 = (const float*)d_in[25];
    const float* fb2 = (const float*)d_in[27];
    const float* g3  = (const float*)d_in[28];
    const float* be3 = (const float*)d_in[29];
    float* out = (float*)d_out;

    float *zp, *o1p, *o2p;
    bf16 *dech,*decl,*ench,*encl,*qh,*ql,*kh,*kl,*vh,*vl;
    bf16 *aoh,*aol,*o1h,*o1l,*o2h,*o2l,*ffh,*ffl,*whp,*wlp;
    cudaGetSymbolAddress((void**)&zp,  g_z);
    cudaGetSymbolAddress((void**)&o1p, g_o1);
    cudaGetSymbolAddress((void**)&o2p, g_o2);
    cudaGetSymbolAddress((void**)&dech, g_dech); cudaGetSymbolAddress((void**)&decl, g_decl);
    cudaGetSymbolAddress((void**)&ench, g_ench); cudaGetSymbolAddress((void**)&encl, g_encl);
    cudaGetSymbolAddress((void**)&qh, g_qh); cudaGetSymbolAddress((void**)&ql, g_ql);
    cudaGetSymbolAddress((void**)&kh, g_kh); cudaGetSymbolAddress((void**)&kl, g_kl);
    cudaGetSymbolAddress((void**)&vh, g_vh); cudaGetSymbolAddress((void**)&vl, g_vl);
    cudaGetSymbolAddress((void**)&aoh,  g_aoh);  cudaGetSymbolAddress((void**)&aol,  g_aol);
    cudaGetSymbolAddress((void**)&o1h,  g_o1h);  cudaGetSymbolAddress((void**)&o1l,  g_o1l);
    cudaGetSymbolAddress((void**)&o2h,  g_o2h);  cudaGetSymbolAddress((void**)&o2l,  g_o2l);
    cudaGetSymbolAddress((void**)&ffh,  g_ffh);  cudaGetSymbolAddress((void**)&ffl,  g_ffl);
    cudaGetSymbolAddress((void**)&whp,  g_wh);   cudaGetSymbolAddress((void**)&wlp,  g_wl);

    cudaFuncSetAttribute(attn_mma,   cudaFuncAttributeMaxDynamicSharedMemorySize, ATT_SMEM);
    cudaFuncSetAttribute(gemm_ts<0>, cudaFuncAttributeMaxDynamicSharedMemorySize, GEMM_SMEM);
    cudaFuncSetAttribute(gemm_ts<1>, cudaFuncAttributeMaxDynamicSharedMemorySize, GEMM_SMEM);
    cudaFuncSetAttribute(gemm_ts<2>, cudaFuncAttributeMaxDynamicSharedMemorySize, GEMM_SMEM);

    const dim3 b(32, 8);
    const dim3 gD (8, 16);     // N=1024  (256x128 CTA tiles)
    const dim3 gFF(32, 16);    // N=4096
    const dim3 gA (SEQ/128, NH, BB);

    // ---- prep, ordered so launch #6 is a gemm_ts (ncu -s 5 -c 1 profiles it) --
    split_act<<<TOK*DM/1024, 256>>>(dec, dech, decl, TOK*DM/4);                    // 1
    split_act<<<TOK*DM/1024, 256>>>(enc, ench, encl, TOK*DM/4);                    // 2
    wsplit_t<<<dim3(32, 32),  b>>>((const float*)d_in[4],  whp + 0*MEG,  wlp + 0*MEG,  DM,  DM);  // 3
    wsplit_t<<<dim3(32, 32),  b>>>((const float*)d_in[6],  whp + 1*MEG,  wlp + 1*MEG,  DM,  DM);  // 4
    wsplit_t<<<dim3(32, 32),  b>>>((const float*)d_in[8],  whp + 2*MEG,  wlp + 2*MEG,  DM,  DM);  // 5
    gemm_ts<2><<<gD, 256, GEMM_SMEM>>>(dech, decl, whp + 0*MEG, wlp + 0*MEG, bq1, 0, qh, ql, DM, DM);  // 6
    wsplit_t<<<dim3(32, 32),  b>>>((const float*)d_in[10], whp + 3*MEG,  wlp + 3*MEG,  DM,  DM);
    wsplit_t<<<dim3(32, 32),  b>>>((const float*)d_in[14], whp + 4*MEG,  wlp + 4*MEG,  DM,  DM);
    wsplit_t<<<dim3(32, 32),  b>>>((const float*)d_in[16], whp + 5*MEG,  wlp + 5*MEG,  DM,  DM);
    wsplit_t<<<dim3(32, 32),  b>>>((const float*)d_in[18], whp + 6*MEG,  wlp + 6*MEG,  DM,  DM);
    wsplit_t<<<dim3(32, 32),  b>>>((const float*)d_in[20], whp + 7*MEG,  wlp + 7*MEG,  DM,  DM);
    wsplit_t<<<dim3(128, 32), b>>>((const float*)d_in[24], whp + 8*MEG,  wlp + 8*MEG,  DM,  FFD);
    wsplit_t<<<dim3(32, 128), b>>>((const float*)d_in[26], whp + 12*MEG, wlp + 12*MEG, FFD, DM);

    // ---- self-attention block ----
    gemm_ts<2><<<gD, 256, GEMM_SMEM>>>(dech, decl, whp + 1*MEG, wlp + 1*MEG, bk1, 0, kh, kl, DM, DM);
    gemm_ts<2><<<gD, 256, GEMM_SMEM>>>(dech, decl, whp + 2*MEG, wlp + 2*MEG, bv1, 0, vh, vl, DM, DM);
    attn_mma<<<gA, 256, ATT_SMEM>>>(qh, ql, kh, kl, vh, vl, aoh, aol, 1);
    gemm_ts<0><<<gD, 256, GEMM_SMEM>>>(aoh, aol, whp + 3*MEG, wlp + 3*MEG, zb1, zp, 0, 0, DM, DM);
    add_ln_kernel<true><<<TOK, 256>>>(zp, dec, g1, be1, o1p, o1h, o1l);

    // ---- cross-attention block ----
    gemm_ts<2><<<gD, 256, GEMM_SMEM>>>(o1h, o1l, whp + 4*MEG, wlp + 4*MEG, bq2, 0, qh, ql, DM, DM);
    gemm_ts<2><<<gD, 256, GEMM_SMEM>>>(ench, encl, whp + 5*MEG, wlp + 5*MEG, bk2, 0, kh, kl, DM, DM);
    gemm_ts<2><<<gD, 256, GEMM_SMEM>>>(ench, encl, whp + 6*MEG, wlp + 6*MEG, bv2, 0, vh, vl, DM, DM);
    attn_mma<<<gA, 256, ATT_SMEM>>>(qh, ql, kh, kl, vh, vl, aoh, aol, 0);
    gemm_ts<0><<<gD, 256, GEMM_SMEM>>>(aoh, aol, whp + 7*MEG, wlp + 7*MEG, zb2, zp, 0, 0, DM, DM);
    add_ln_kernel<true><<<TOK, 256>>>(zp, o1p, g2, be2, o2p, o2h, o2l);

    // ---- feed-forward block ----
    gemm_ts<1><<<gFF, 256, GEMM_SMEM>>>(o2h, o2l, whp + 8*MEG,  wlp + 8*MEG,  fb1, 0, ffh, ffl, FFD, DM);
    gemm_ts<0><<<gD,  256, GEMM_SMEM>>>(ffh, ffl, whp + 12*MEG, wlp + 12*MEG, fb2, zp, 0, 0, DM, FFD);
    add_ln_kernel<false><<<TOK, 256>>>(zp, o2p, g3, be3, out, 0, 0);
}

// round 9
// speedup vs baseline: 2.2014x; 1.0018x over previous
#include <cuda_runtime.h>
#include <cuda_bf16.h>
#include <math.h>
#include <stdint.h>

// Problem constants
#define BB   4
#define SEQ  1024
#define DM   1024
#define NH   16
#define HD   64
#define FFD  4096
#define TOK  (BB*SEQ)   // 4096
#define MEG  (1024*1024)

typedef __nv_bfloat16 bf16;

// ---------------- scratch (device globals: no allocs allowed) ----------------
__device__ float g_z  [TOK*DM];
__device__ float g_o1 [TOK*DM];
__device__ float g_o2 [TOK*DM];
__device__ float g_b3 [3*DM];
__device__ float g_b2 [2*DM];
__device__ bf16  g_dech[TOK*DM], g_decl[TOK*DM];
__device__ bf16  g_ench[TOK*DM], g_encl[TOK*DM];
__device__ bf16  g_qkvh[TOK*3*DM], g_qkvl[TOK*3*DM];   // self QKV packed / cross KV packed
__device__ bf16  g_qh [TOK*DM], g_ql [TOK*DM];          // cross Q
__device__ bf16  g_aoh [TOK*DM], g_aol [TOK*DM];
__device__ bf16  g_o1h [TOK*DM], g_o1l [TOK*DM];
__device__ bf16  g_o2h [TOK*DM], g_o2l [TOK*DM];
__device__ bf16  g_ffh [TOK*FFD], g_ffl[TOK*FFD];
__device__ bf16  g_wh[16*MEG], g_wl[16*MEG];

// ==================== low-level helpers (sm_100 baseline ISA) =================
__device__ __forceinline__ uint32_t smem_u32(const void* p) {
    uint32_t a;
    asm("{ .reg .u64 t; cvta.to.shared.u64 t, %1; cvt.u32.u64 %0, t; }" : "=r"(a) : "l"(p));
    return a;
}
__device__ __forceinline__ void cpa16(uint32_t s, const void* g) {
    asm volatile("cp.async.cg.shared.global [%0], [%1], 16;" :: "r"(s), "l"(g));
}
#define CPA_COMMIT() asm volatile("cp.async.commit_group;" ::: "memory")
#define CPA_WAIT1()  asm volatile("cp.async.wait_group 1;"  ::: "memory")
#define CPA_WAIT2()  asm volatile("cp.async.wait_group 2;"  ::: "memory")

#define LDSM4(r, a) \
    asm volatile("ldmatrix.sync.aligned.m8n8.x4.shared.b16 {%0,%1,%2,%3}, [%4];" \
        : "=r"((r)[0]), "=r"((r)[1]), "=r"((r)[2]), "=r"((r)[3]) : "r"(a))
#define LDSM4T(r, a) \
    asm volatile("ldmatrix.sync.aligned.m8n8.x4.trans.shared.b16 {%0,%1,%2,%3}, [%4];" \
        : "=r"((r)[0]), "=r"((r)[1]), "=r"((r)[2]), "=r"((r)[3]) : "r"(a))

#define MMA16816(c, a, b0, b1) \
    asm volatile("mma.sync.aligned.m16n8k16.row.col.f32.bf16.bf16.f32 " \
        "{%0,%1,%2,%3},{%4,%5,%6,%7},{%8,%9},{%0,%1,%2,%3};" \
        : "+f"((c)[0]), "+f"((c)[1]), "+f"((c)[2]), "+f"((c)[3]) \
        : "r"((a)[0]), "r"((a)[1]), "r"((a)[2]), "r"((a)[3]), "r"(b0), "r"(b1))

__device__ __forceinline__ void split1(float x, bf16& h, bf16& l) {
    h = __float2bfloat16_rn(x);
    l = __float2bfloat16_rn(x - __bfloat162float(h));
}
__device__ __forceinline__ uint32_t packsplit(float x, float y, uint32_t& lo) {
    __nv_bfloat162 h2 = __floats2bfloat162_rn(x, y);
    float2 hf = __bfloat1622float2(h2);
    __nv_bfloat162 l2 = __floats2bfloat162_rn(x - hf.x, y - hf.y);
    lo = *reinterpret_cast<uint32_t*>(&l2);
    return *reinterpret_cast<uint32_t*>(&h2);
}

// ============ weight transpose + bf16 split: W[K,N] -> Th/Tl[N,K] =============
__global__ __launch_bounds__(256)
void wsplit_t(const float* __restrict__ W, bf16* __restrict__ Th,
              bf16* __restrict__ Tl, int K, int N)
{
    __shared__ float t[32][33];
    const int n0 = blockIdx.x * 32, k0 = blockIdx.y * 32;
    const int tx = threadIdx.x, ty = threadIdx.y;   // 32 x 8
#pragma unroll
    for (int i = 0; i < 4; i++)
        t[ty + i*8][tx] = W[(size_t)(k0 + ty + i*8) * N + n0 + tx];
    __syncthreads();
#pragma unroll
    for (int i = 0; i < 4; i++) {
        const int r = ty + i*8;
        const float v = t[tx][r];
        bf16 h, l; split1(v, h, l);
        Th[(size_t)(n0 + r) * K + k0 + tx] = h;
        Tl[(size_t)(n0 + r) * K + k0 + tx] = l;
    }
}

// ============ activation split: X fp32 [n] -> Xh, Xl bf16 =====================
__global__ __launch_bounds__(256)
void split_act(const float* __restrict__ X, bf16* __restrict__ Xh,
               bf16* __restrict__ Xl, int n4)
{
    const int i = blockIdx.x * 256 + threadIdx.x;
    if (i >= n4) return;
    const float4 v = ((const float4*)X)[i];
    bf16 h0,l0,h1,l1,h2,l2,h3,l3;
    split1(v.x,h0,l0); split1(v.y,h1,l1); split1(v.z,h2,l2); split1(v.w,h3,l3);
    __nv_bfloat162 ph[2] = {{h0,h1},{h2,h3}};
    __nv_bfloat162 pl[2] = {{l0,l1},{l2,l3}};
    ((uint2*)Xh)[i] = *(uint2*)ph;
    ((uint2*)Xl)[i] = *(uint2*)pl;
}

// ============ bias concat: [bq|bk|bv] -> b3, [bk2|bv2] -> b2 ==================
__global__ __launch_bounds__(256)
void biascat(const float* __restrict__ bq, const float* __restrict__ bk,
             const float* __restrict__ bv, float* __restrict__ b3,
             const float* __restrict__ bk2, const float* __restrict__ bv2,
             float* __restrict__ b2)
{
    const int i = blockIdx.x * 256 + threadIdx.x;   // 0..1023
    b3[i]        = bq[i];
    b3[DM + i]   = bk[i];
    b3[2*DM + i] = bv[i];
    b2[i]        = bk2[i];
    b2[DM + i]   = bv2[i];
}

// ========== mma.sync GEMM: C[M,N] = A @ W + bias ==============================
// CTA 256x128, 8 warps (warp tile 64x64), BK=32, 4-stage cp.async pipeline.
// OUT=0: fp32 C + bias.  OUT=1: relu(C+bias) -> bf16 hi/lo.  OUT=2: C+bias -> bf16 hi/lo.
#define GEMM_SMEM (4*49152)   // 196608

template<int OUT>
__global__ __launch_bounds__(256)
void gemm_ts(const bf16* __restrict__ Ah, const bf16* __restrict__ Al,
             const bf16* __restrict__ Bh, const bf16* __restrict__ Bl,
             const float* __restrict__ bias, float* __restrict__ C,
             bf16* __restrict__ Ch, bf16* __restrict__ Cl, int N, int K)
{
    extern __shared__ char smraw[];
    const uint32_t sb0 = smem_u32(smraw);          // 4 stages x 49152 B
    const int tid  = threadIdx.x;
    const int lane = tid & 31;
    const int w    = tid >> 5;
    const int m0   = blockIdx.y * 256;
    const int n0   = blockIdx.x * 128;
    const int wm   = (w >> 1) * 64;     // 4 warp-rows
    const int wn   = (w & 1) * 64;      // 2 warp-cols
    const int r15  = lane & 15;
    const int kh   = lane >> 4;

    uint32_t aoff[4][2], boff[4][2];
#pragma unroll
    for (int bm = 0; bm < 4; bm++) {
        const int row = wm + bm*16 + r15;
        const int sw  = (row >> 1) & 3;
#pragma unroll
        for (int ks = 0; ks < 2; ks++)
            aoff[bm][ks] = row*64 + (((ks*2 + kh) ^ sw) << 4);
    }
#pragma unroll
    for (int bp = 0; bp < 4; bp++) {
        const int row = wn + bp*16 + r15;
        const int sw  = (row >> 1) & 3;
#pragma unroll
        for (int ks = 0; ks < 2; ks++)
            boff[bp][ks] = row*64 + (((ks*2 + kh) ^ sw) << 4);
    }

    const bf16* gA[2] = {Ah + (size_t)m0*K, Al + (size_t)m0*K};
    const bf16* gB[2] = {Bh + (size_t)n0*K, Bl + (size_t)n0*K};
    auto load_stage = [&](int s, int k0) {
        const uint32_t stb = sb0 + s*49152;
#pragma unroll
        for (int t = 0; t < 2; t++) {
#pragma unroll
            for (int i = 0; i < 4; i++) {
                const int idx = i*256 + tid;
                const int row = idx >> 2;
                const int cc  = idx & 3;
                const int sc  = cc ^ ((row >> 1) & 3);
                cpa16(stb + t*16384 + row*64 + sc*16,
                      gA[t] + (size_t)row*K + k0 + cc*8);
            }
        }
#pragma unroll
        for (int t = 0; t < 2; t++) {
#pragma unroll
            for (int i = 0; i < 2; i++) {
                const int idx = i*256 + tid;
                const int row = idx >> 2;
                const int cc  = idx & 3;
                const int sc  = cc ^ ((row >> 1) & 3);
                cpa16(stb + 32768 + t*8192 + row*64 + sc*16,
                      gB[t] + (size_t)row*K + k0 + cc*8);
            }
        }
    };

    float acc[4][8][4];
#pragma unroll
    for (int bm = 0; bm < 4; bm++)
#pragma unroll
        for (int bn = 0; bn < 8; bn++)
#pragma unroll
            for (int j = 0; j < 4; j++) acc[bm][bn][j] = 0.f;

    const int CH = K >> 5;
    load_stage(0, 0);  CPA_COMMIT();
    load_stage(1, 32); CPA_COMMIT();
    load_stage(2, 64); CPA_COMMIT();

    for (int c = 0; c < CH; ++c) {
        CPA_WAIT2();
        __syncthreads();
        if (c + 3 < CH) load_stage((c + 3) & 3, (c + 3) * 32);
        CPA_COMMIT();

        const uint32_t stb = sb0 + (c & 3)*49152;
#pragma unroll
        for (int ks = 0; ks < 2; ks++) {
            uint32_t ah[4][4], al[4][4], bh[4][4], bl[4][4];
#pragma unroll
            for (int bm = 0; bm < 4; bm++) {
                LDSM4(ah[bm], stb +         aoff[bm][ks]);
                LDSM4(al[bm], stb + 16384 + aoff[bm][ks]);
            }
#pragma unroll
            for (int bp = 0; bp < 4; bp++) {
                LDSM4(bh[bp], stb + 32768 + boff[bp][ks]);
                LDSM4(bl[bp], stb + 40960 + boff[bp][ks]);
            }
#pragma unroll
            for (int bm = 0; bm < 4; bm++)
#pragma unroll
                for (int bp = 0; bp < 4; bp++)
#pragma unroll
                    for (int sel = 0; sel < 2; sel++) {
                        const int bn = bp*2 + sel;
                        MMA16816(acc[bm][bn], ah[bm], bh[bp][sel], bh[bp][sel+2]);
                        MMA16816(acc[bm][bn], ah[bm], bl[bp][sel], bl[bp][sel+2]);
                        MMA16816(acc[bm][bn], al[bm], bh[bp][sel], bh[bp][sel+2]);
                    }
        }
    }

    const int er = lane >> 2;
    const int ec = (lane & 3) * 2;
#pragma unroll
    for (int bm = 0; bm < 4; bm++)
#pragma unroll
        for (int bn = 0; bn < 8; bn++) {
            const int col = n0 + wn + bn*8 + ec;
            const float b0 = bias[col], b1 = bias[col+1];
#pragma unroll
            for (int half = 0; half < 2; half++) {
                const int r = m0 + wm + bm*16 + er + half*8;
                float v0 = acc[bm][bn][half*2+0] + b0;
                float v1 = acc[bm][bn][half*2+1] + b1;
                if (OUT == 0) {
                    float2 o = {v0, v1};
                    *(float2*)&C[(size_t)r*N + col] = o;
                } else {
                    if (OUT == 1) { v0 = fmaxf(v0, 0.f); v1 = fmaxf(v1, 0.f); }
                    uint32_t lo;
                    uint32_t hi = packsplit(v0, v1, lo);
                    *(uint32_t*)&Ch[(size_t)r*N + col] = hi;
                    *(uint32_t*)&Cl[(size_t)r*N + col] = lo;
                }
            }
        }
}

// ---------------- fused residual add + LayerNorm (row = 1024) ----------------
template<bool SPLIT>
__global__ __launch_bounds__(256)
void add_ln_kernel(const float* __restrict__ z, const float* __restrict__ res,
                   const float* __restrict__ g, const float* __restrict__ be,
                   float* __restrict__ out, bf16* __restrict__ oh, bf16* __restrict__ ol)
{
    const int row = blockIdx.x;
    const int tid = threadIdx.x;
    const float* zr = z   + (size_t)row*DM;
    const float* rr = res + (size_t)row*DM;

    float v[4];
    float s = 0.f, sq = 0.f;
#pragma unroll
    for (int i = 0; i < 4; i++) {
        const int c = tid + i*256;
        const float x = zr[c] + rr[c];
        v[i] = x; s += x; sq += x*x;
    }
#pragma unroll
    for (int o = 16; o; o >>= 1) {
        s  += __shfl_xor_sync(0xffffffffu, s,  o);
        sq += __shfl_xor_sync(0xffffffffu, sq, o);
    }
    __shared__ float ss[8], ssq[8];
    if ((tid & 31) == 0) { ss[tid >> 5] = s; ssq[tid >> 5] = sq; }
    __syncthreads();
    if (tid < 32) {
        s  = (tid < 8) ? ss[tid]  : 0.f;
        sq = (tid < 8) ? ssq[tid] : 0.f;
#pragma unroll
        for (int o = 4; o; o >>= 1) {
            s  += __shfl_xor_sync(0xffffffffu, s,  o);
            sq += __shfl_xor_sync(0xffffffffu, sq, o);
        }
        if (tid == 0) { ss[0] = s; ssq[0] = sq; }
    }
    __syncthreads();
    const float mean = ss[0] * (1.f/DM);
    const float var  = ssq[0] * (1.f/DM) - mean*mean;
    const float inv  = rsqrtf(var + 1e-5f);
#pragma unroll
    for (int i = 0; i < 4; i++) {
        const int c = tid + i*256;
        const float y = (v[i] - mean)*inv*g[c] + be[c];
        out[(size_t)row*DM + c] = y;
        if (SPLIT) {
            bf16 h, l; split1(y, h, l);
            oh[(size_t)row*DM + c] = h;
            ol[(size_t)row*DM + c] = l;
        }
    }
}

// ---------------- mma.sync flash attention -----------------------------------
// ldq / ldkv: row strides of the packed Q / KV buffers (elements).
#define ATT_SMEM (32768 + 2*32768)

__global__ __launch_bounds__(256, 2)
void attn_mma(const bf16* __restrict__ Qhg, const bf16* __restrict__ Qlg,
              const bf16* __restrict__ Khg, const bf16* __restrict__ Klg,
              const bf16* __restrict__ Vhg, const bf16* __restrict__ Vlg,
              bf16* __restrict__ Oh, bf16* __restrict__ Ol,
              int causal, int ldq, int ldkv)
{
    extern __shared__ char smraw[];
    const uint32_t Qs = smem_u32(smraw);
    const uint32_t St = Qs + 32768;

    const int qi = blockIdx.x, h = blockIdx.y, b = blockIdx.z;
    const int tid = threadIdx.x, lane = tid & 31, w = tid >> 5;
    const int q0 = qi * 128;
    const int wq = w * 16;
    const int rA = lane & 15, gh = lane >> 4;
    const int r4 = lane >> 2, c2 = (lane & 3) * 2;

    {
        const bf16* qsrc[2] = {Qhg, Qlg};
#pragma unroll
        for (int it = 0; it < 8; it++) {
            const int idx = tid + it*256;
            const int tile = idx >> 10, row = (idx >> 3) & 127, g = idx & 7;
            cpa16(Qs + tile*16384 + row*128 + ((g ^ (row & 7)) << 4),
                  qsrc[tile] + (size_t)(b*SEQ + q0 + row)*ldq + h*HD + g*8);
        }
    }
    CPA_COMMIT();

    const bf16* ksrc[4] = {Khg, Klg, Vhg, Vlg};
    auto load_kv = [&](int s, int k0) {
#pragma unroll
        for (int it = 0; it < 8; it++) {
            const int idx = tid + it*256;
            const int tile = idx >> 9, row = (idx >> 3) & 63, g = idx & 7;
            cpa16(St + s*32768 + tile*8192 + row*128 + ((g ^ (row & 7)) << 4),
                  ksrc[tile] + (size_t)(b*SEQ + k0 + row)*ldkv + h*HD + g*8);
        }
    };

    const int nt = causal ? (qi*2 + 2) : (SEQ/64);
    load_kv(0, 0);  CPA_COMMIT();
    if (nt > 1) load_kv(1, 64);
    CPA_COMMIT();

    float oacc[8][4];
#pragma unroll
    for (int n = 0; n < 8; n++)
#pragma unroll
        for (int j = 0; j < 4; j++) oacc[n][j] = 0.f;
    float m0 = -1e30f, m1 = -1e30f, l0 = 0.f, l1 = 0.f;

    const int qrow = wq + rA;
    const uint32_t qx  = (uint32_t)qrow * 128;
    const int      qxr = qrow & 7;
    const uint32_t kx  = (uint32_t)rA * 128;
    const int      kxr = rA & 7;

    for (int kt = 0; kt < nt; kt++) {
        CPA_WAIT1();
        __syncthreads();
        const uint32_t stb = St + (kt & 1)*32768;
        const int k0 = kt * 64;

        float sacc[8][4];
#pragma unroll
        for (int n = 0; n < 8; n++)
#pragma unroll
            for (int j = 0; j < 4; j++) sacc[n][j] = 0.f;
#pragma unroll
        for (int ks = 0; ks < 4; ks++) {
            uint32_t qh_[4], ql_[4];
            const uint32_t qo = qx + (((ks*2 + gh) ^ qxr) << 4);
            LDSM4(qh_, Qs + qo);
            LDSM4(ql_, Qs + 16384 + qo);
#pragma unroll
            for (int bp = 0; bp < 4; bp++) {
                uint32_t kh_[4], kl_[4];
                const uint32_t ko = stb + bp*2048 + kx + (((ks*2 + gh) ^ kxr) << 4);
                LDSM4(kh_, ko);
                LDSM4(kl_, ko + 8192);
#pragma unroll
                for (int sel = 0; sel < 2; sel++) {
                    const int n = bp*2 + sel;
                    MMA16816(sacc[n], qh_, kh_[sel], kh_[sel+2]);
                    MMA16816(sacc[n], qh_, kl_[sel], kl_[sel+2]);
                    MMA16816(sacc[n], ql_, kh_[sel], kh_[sel+2]);
                }
            }
        }

        const int growA = q0 + wq + r4;
#pragma unroll
        for (int n = 0; n < 8; n++)
#pragma unroll
            for (int j = 0; j < 4; j++) sacc[n][j] *= 0.125f;
        if (causal && (k0 + 63 > q0)) {
#pragma unroll
            for (int n = 0; n < 8; n++) {
                const int col = k0 + n*8 + c2;
                if (col     > growA)     sacc[n][0] = -1e9f;
                if (col + 1 > growA)     sacc[n][1] = -1e9f;
                if (col     > growA + 8) sacc[n][2] = -1e9f;
                if (col + 1 > growA + 8) sacc[n][3] = -1e9f;
            }
        }

        float tm0 = -1e30f, tm1 = -1e30f;
#pragma unroll
        for (int n = 0; n < 8; n++) {
            tm0 = fmaxf(tm0, fmaxf(sacc[n][0], sacc[n][1]));
            tm1 = fmaxf(tm1, fmaxf(sacc[n][2], sacc[n][3]));
        }
        tm0 = fmaxf(tm0, __shfl_xor_sync(0xffffffffu, tm0, 1));
        tm0 = fmaxf(tm0, __shfl_xor_sync(0xffffffffu, tm0, 2));
        tm1 = fmaxf(tm1, __shfl_xor_sync(0xffffffffu, tm1, 1));
        tm1 = fmaxf(tm1, __shfl_xor_sync(0xffffffffu, tm1, 2));
        const float mn0 = fmaxf(m0, tm0), mn1 = fmaxf(m1, tm1);
        const float a0 = __expf(m0 - mn0), a1 = __expf(m1 - mn1);
        float ps0 = 0.f, ps1 = 0.f;
#pragma unroll
        for (int n = 0; n < 8; n++) {
            sacc[n][0] = __expf(sacc[n][0] - mn0);
            sacc[n][1] = __expf(sacc[n][1] - mn0);
            sacc[n][2] = __expf(sacc[n][2] - mn1);
            sacc[n][3] = __expf(sacc[n][3] - mn1);
            ps0 += sacc[n][0] + sacc[n][1];
            ps1 += sacc[n][2] + sacc[n][3];
        }
        ps0 += __shfl_xor_sync(0xffffffffu, ps0, 1);
        ps0 += __shfl_xor_sync(0xffffffffu, ps0, 2);
        ps1 += __shfl_xor_sync(0xffffffffu, ps1, 1);
        ps1 += __shfl_xor_sync(0xffffffffu, ps1, 2);
        l0 = l0*a0 + ps0;  l1 = l1*a1 + ps1;
        m0 = mn0;          m1 = mn1;
#pragma unroll
        for (int n = 0; n < 8; n++) {
            oacc[n][0] *= a0; oacc[n][1] *= a0;
            oacc[n][2] *= a1; oacc[n][3] *= a1;
        }

        uint32_t pha[4][4], pla[4][4];
#pragma unroll
        for (int ks = 0; ks < 4; ks++) {
            const int n0b = 2*ks, n1b = n0b + 1;
            pha[ks][0] = packsplit(sacc[n0b][0], sacc[n0b][1], pla[ks][0]);
            pha[ks][1] = packsplit(sacc[n0b][2], sacc[n0b][3], pla[ks][1]);
            pha[ks][2] = packsplit(sacc[n1b][0], sacc[n1b][1], pla[ks][2]);
            pha[ks][3] = packsplit(sacc[n1b][2], sacc[n1b][3], pla[ks][3]);
        }

#pragma unroll
        for (int ks = 0; ks < 4; ks++) {
#pragma unroll
            for (int gp = 0; gp < 4; gp++) {
                uint32_t vh_[4], vl_[4];
                const uint32_t vo = stb + 16384 + (uint32_t)(ks*16 + rA)*128
                                  + (((gp*2 + gh) ^ kxr) << 4);
                LDSM4T(vh_, vo);
                LDSM4T(vl_, vo + 8192);
                const int n = gp*2;
                MMA16816(oacc[n],   pha[ks], vh_[0], vh_[1]);
                MMA16816(oacc[n+1], pha[ks], vh_[2], vh_[3]);
                MMA16816(oacc[n],   pla[ks], vh_[0], vh_[1]);
                MMA16816(oacc[n+1], pla[ks], vh_[2], vh_[3]);
                MMA16816(oacc[n],   pha[ks], vl_[0], vl_[1]);
                MMA16816(oacc[n+1], pha[ks], vl_[2], vl_[3]);
            }
        }
        __syncthreads();
        if (kt + 2 < nt) load_kv(kt & 1, (kt + 2)*64);
        CPA_COMMIT();
    }

    const float il0 = 1.f / l0, il1 = 1.f / l1;
    const size_t row0 = (size_t)(b*SEQ + q0 + wq + r4)*DM + h*HD;
    const size_t row1 = row0 + (size_t)8*DM;
#pragma unroll
    for (int n = 0; n < 8; n++) {
        const int col = n*8 + c2;
        uint32_t lo0, lo1;
        const uint32_t hi0 = packsplit(oacc[n][0]*il0, oacc[n][1]*il0, lo0);
        const uint32_t hi1 = packsplit(oacc[n][2]*il1, oacc[n][3]*il1, lo1);
        *(uint32_t*)&Oh[row0 + col] = hi0;
        *(uint32_t*)&Ol[row0 + col] = lo0;
        *(uint32_t*)&Oh[row1 + col] = hi1;
        *(uint32_t*)&Ol[row1 + col] = lo1;
    }
}

// ---------------- launch ------------------------------------------------------
extern "C" void kernel_launch(void* const* d_in, const int* in_sizes, int n_in,
                              void* d_out, int out_size)
{
    (void)in_sizes; (void)n_in; (void)out_size;
    const float* dec = (const float*)d_in[0];
    const float* enc = (const float*)d_in[1];
    const float* bq1 = (const float*)d_in[5];
    const float* bk1 = (const float*)d_in[7];
    const float* bv1 = (const float*)d_in[9];
    const float* zb1 = (const float*)d_in[11];
    const float* g1  = (const float*)d_in[12];
    const float* be1 = (const float*)d_in[13];
    const float* bq2 = (const float*)d_in[15];
    const float* bk2 = (const float*)d_in[17];
    const float* bv2 = (const float*)d_in[19];
    const float* zb2 = (const float*)d_in[21];
    const float* g2  = (const float*)d_in[22];
    const float* be2 = (const float*)d_in[23];
    const float* fb1 = (const float*)d_in[25];
    const float* fb2 = (const float*)d_in[27];
    const float* g3  = (const float*)d_in[28];
    const float* be3 = (const float*)d_in[29];
    float* out = (float*)d_out;

    float *zp, *o1p, *o2p, *b3p, *b2p;
    bf16 *dech,*decl,*ench,*encl,*qkvh,*qkvl,*qh,*ql;
    bf16 *aoh,*aol,*o1h,*o1l,*o2h,*o2l,*ffh,*ffl,*whp,*wlp;
    cudaGetSymbolAddress((void**)&zp,  g_z);
    cudaGetSymbolAddress((void**)&o1p, g_o1);
    cudaGetSymbolAddress((void**)&o2p, g_o2);
    cudaGetSymbolAddress((void**)&b3p, g_b3);
    cudaGetSymbolAddress((void**)&b2p, g_b2);
    cudaGetSymbolAddress((void**)&dech, g_dech); cudaGetSymbolAddress((void**)&decl, g_decl);
    cudaGetSymbolAddress((void**)&ench, g_ench); cudaGetSymbolAddress((void**)&encl, g_encl);
    cudaGetSymbolAddress((void**)&qkvh, g_qkvh); cudaGetSymbolAddress((void**)&qkvl, g_qkvl);
    cudaGetSymbolAddress((void**)&qh, g_qh); cudaGetSymbolAddress((void**)&ql, g_ql);
    cudaGetSymbolAddress((void**)&aoh,  g_aoh);  cudaGetSymbolAddress((void**)&aol,  g_aol);
    cudaGetSymbolAddress((void**)&o1h,  g_o1h);  cudaGetSymbolAddress((void**)&o1l,  g_o1l);
    cudaGetSymbolAddress((void**)&o2h,  g_o2h);  cudaGetSymbolAddress((void**)&o2l,  g_o2l);
    cudaGetSymbolAddress((void**)&ffh,  g_ffh);  cudaGetSymbolAddress((void**)&ffl,  g_ffl);
    cudaGetSymbolAddress((void**)&whp,  g_wh);   cudaGetSymbolAddress((void**)&wlp,  g_wl);

    cudaFuncSetAttribute(attn_mma,   cudaFuncAttributeMaxDynamicSharedMemorySize, ATT_SMEM);
    cudaFuncSetAttribute(gemm_ts<0>, cudaFuncAttributeMaxDynamicSharedMemorySize, GEMM_SMEM);
    cudaFuncSetAttribute(gemm_ts<1>, cudaFuncAttributeMaxDynamicSharedMemorySize, GEMM_SMEM);
    cudaFuncSetAttribute(gemm_ts<2>, cudaFuncAttributeMaxDynamicSharedMemorySize, GEMM_SMEM);

    const dim3 b(32, 8);
    const dim3 gD  (8, 16);    // N=1024  (256x128 CTA tiles)
    const dim3 gQKV(24, 16);   // N=3072
    const dim3 gKV (16, 16);   // N=2048
    const dim3 gFF (32, 16);   // N=4096
    const dim3 gA  (SEQ/128, NH, BB);

    // ---- prep (fused QKV gemm at our launch #6) ----
    wsplit_t<<<dim3(32, 32),  b>>>((const float*)d_in[4],  whp + 0*MEG,  wlp + 0*MEG,  DM,  DM);  // 1 wq1
    wsplit_t<<<dim3(32, 32),  b>>>((const float*)d_in[6],  whp + 1*MEG,  wlp + 1*MEG,  DM,  DM);  // 2 wk1
    wsplit_t<<<dim3(32, 32),  b>>>((const float*)d_in[8],  whp + 2*MEG,  wlp + 2*MEG,  DM,  DM);  // 3 wv1
    split_act<<<TOK*DM/1024, 256>>>(dec, dech, decl, TOK*DM/4);                                    // 4
    biascat<<<4, 256>>>(bq1, bk1, bv1, b3p, bk2, bv2, b2p);                                        // 5
    // 6: fused self QKV (B rows 0..3071 span wq1|wk1|wv1 transposed, contiguous)
    gemm_ts<2><<<gQKV, 256, GEMM_SMEM>>>(dech, decl, whp + 0*MEG, wlp + 0*MEG, b3p, 0, qkvh, qkvl, 3*DM, DM);
    wsplit_t<<<dim3(32, 32),  b>>>((const float*)d_in[10], whp + 3*MEG,  wlp + 3*MEG,  DM,  DM);  // zw1
    wsplit_t<<<dim3(32, 32),  b>>>((const float*)d_in[14], whp + 4*MEG,  wlp + 4*MEG,  DM,  DM);  // wq2
    wsplit_t<<<dim3(32, 32),  b>>>((const float*)d_in[16], whp + 5*MEG,  wlp + 5*MEG,  DM,  DM);  // wk2
    wsplit_t<<<dim3(32, 32),  b>>>((const float*)d_in[18], whp + 6*MEG,  wlp + 6*MEG,  DM,  DM);  // wv2
    wsplit_t<<<dim3(32, 32),  b>>>((const float*)d_in[20], whp + 7*MEG,  wlp + 7*MEG,  DM,  DM);  // zw2
    wsplit_t<<<dim3(128, 32), b>>>((const float*)d_in[24], whp + 8*MEG,  wlp + 8*MEG,  DM,  FFD); // fw1
    wsplit_t<<<dim3(32, 128), b>>>((const float*)d_in[26], whp + 12*MEG, wlp + 12*MEG, FFD, DM);  // fw2
    split_act<<<TOK*DM/1024, 256>>>(enc, ench, encl, TOK*DM/4);

    // ---- self-attention block (Q/K/V packed in qkv, stride 3*DM) ----
    attn_mma<<<gA, 256, ATT_SMEM>>>(qkvh, qkvl, qkvh + DM, qkvl + DM, qkvh + 2*DM, qkvl + 2*DM,
                                    aoh, aol, 1, 3*DM, 3*DM);
    gemm_ts<0><<<gD, 256, GEMM_SMEM>>>(aoh, aol, whp + 3*MEG, wlp + 3*MEG, zb1, zp, 0, 0, DM, DM);
    add_ln_kernel<true><<<TOK, 256>>>(zp, dec, g1, be1, o1p, o1h, o1l);

    // ---- cross-attention block (K2|V2 fused, packed in qkv buffer, stride 2*DM) ----
    gemm_ts<2><<<gD, 256, GEMM_SMEM>>>(o1h, o1l, whp + 4*MEG, wlp + 4*MEG, bq2, 0, qh, ql, DM, DM);
    gemm_ts<2><<<gKV, 256, GEMM_SMEM>>>(ench, encl, whp + 5*MEG, wlp + 5*MEG, b2p, 0, qkvh, qkvl, 2*DM, DM);
    attn_mma<<<gA, 256, ATT_SMEM>>>(qh, ql, qkvh, qkvl, qkvh + DM, qkvl + DM,
                                    aoh, aol, 0, DM, 2*DM);
    gemm_ts<0><<<gD, 256, GEMM_SMEM>>>(aoh, aol, whp + 7*MEG, wlp + 7*MEG, zb2, zp, 0, 0, DM, DM);
    add_ln_kernel<true><<<TOK, 256>>>(zp, o1p, g2, be2, o2p, o2h, o2l);

    // ---- feed-forward block ----
    gemm_ts<1><<<gFF, 256, GEMM_SMEM>>>(o2h, o2l, whp + 8*MEG,  wlp + 8*MEG,  fb1, 0, ffh, ffl, FFD, DM);
    gemm_ts<0><<<gD,  256, GEMM_SMEM>>>(ffh, ffl, whp + 12*MEG, wlp + 12*MEG, fb2, zp, 0, 0, DM, FFD);
    add_ln_kernel<false><<<TOK, 256>>>(zp, o2p, g3, be3, out, 0, 0);
}